// round 14
// baseline (speedup 1.0000x reference)
#include <cuda_runtime.h>
#include <cuda_fp16.h>
#include <math.h>
#include <stdint.h>

#define N_SRC 16384
#define N_DST 8192
#define KNB 32
#define E_TOT (N_DST*KNB)
#define T 16
#define H 64
#define TILE 64

// ---- scratch ----
__device__ __half g_eout[(size_t)E_TOT*H];
__device__ __half g_aout[(size_t)E_TOT*H];
__device__ float g_P[N_SRC*H];
__device__ float g_Q[N_DST*H];
__device__ int   g_list[E_TOT];
__device__ int   g_part[128][16];
__device__ int   g_cur[T];
__device__ __half g_B[2][256][88];
__device__ float  g_bias[2][256];
__device__ float  g_tv[16];

// ---- LSTM smem byte map (per CTA) ----
#define OFF_B    0
#define OFF_A    0
#define ABUF     11264
#define OFF_SIDX 45056
#define OFF_SLEN 45312
#define OFF_TV   45568
#define OFF_SMAX 45632
#define LSTM_SMEM 45696

// ---- fused edge+dst smem byte map ----
#define FO_EO    0          // 128 x 144B fp16 e_out
#define FO_W2    18432      // 64 x 144B fp16 W2
#define FO_MS    27648      // 128 x 66 fp32 m
#define FO_NW2   61440      // 64 x 64 fp32 nW2t
#define FO_ATT   77824      // 64 f
#define FO_BSH   78080      // 64 f
#define FO_AS    78336      // 128 f
#define FO_AL    78848      // 4 x 32 f
#define FO_HNS   79360      // 4 x 64 f
#define FUSED_SMEM 80384

__device__ __forceinline__ uint32_t smem_u32(const void* p){
    uint32_t a; asm("{ .reg .u64 t; cvta.to.shared.u64 t, %1; cvt.u32.u64 %0, t; }":"=r"(a):"l"(p)); return a;
}
__device__ __forceinline__ uint32_t amat(uint32_t base, int row, int ch){
    return base + (uint32_t)row*176u + ((uint32_t)ch << 4);
}
__device__ __forceinline__ uint32_t ael(uint32_t base, int row, int k){
    return base + (uint32_t)row*176u + ((uint32_t)k << 1);
}
__device__ __forceinline__ void ldm4(uint32_t addr, uint32_t &r0, uint32_t &r1, uint32_t &r2, uint32_t &r3){
    asm volatile("ldmatrix.sync.aligned.m8n8.x4.shared.b16 {%0,%1,%2,%3}, [%4];"
        : "=r"(r0),"=r"(r1),"=r"(r2),"=r"(r3) : "r"(addr));
}
__device__ __forceinline__ void mma_fp16(float* c, uint32_t a0,uint32_t a1,uint32_t a2,uint32_t a3,
                                         uint32_t b0, uint32_t b1){
    asm volatile("mma.sync.aligned.m16n8k16.row.col.f32.f16.f16.f32 "
        "{%0,%1,%2,%3}, {%4,%5,%6,%7}, {%8,%9}, {%0,%1,%2,%3};"
        : "+f"(c[0]),"+f"(c[1]),"+f"(c[2]),"+f"(c[3])
        : "r"(a0),"r"(a1),"r"(a2),"r"(a3),"r"(b0),"r"(b1));
}
__device__ __forceinline__ __half2 tanh2(__half2 x){
    uint32_t xi = *(uint32_t*)&x, yi;
    asm("tanh.approx.f16x2 %0, %1;" : "=r"(yi) : "r"(xi));
    return *(__half2*)&yi;
}
__device__ __forceinline__ uint32_t pack_h2(float a, float b){
    __half2 v; v.x = __float2half_rn(a); v.y = __float2half_rn(b);
    return *(uint32_t*)&v;
}

// ---- bucketing ----
__global__ void hist_part_kernel(const int* __restrict__ elen){
    __shared__ int h[T];
    if (threadIdx.x < T) h[threadIdx.x] = 0;
    __syncthreads();
    int base = blockIdx.x * 2048;
    for (int i = threadIdx.x; i < 2048; i += 256) atomicAdd(&h[elen[base + i] - 1], 1);
    __syncthreads();
    if (threadIdx.x < T) g_part[blockIdx.x][threadIdx.x] = h[threadIdx.x];
}
__global__ void scan2_kernel(){
    __shared__ int cnt[T];
    if (threadIdx.x < T){
        int s = 0;
        for (int b = 0; b < 128; b++) s += g_part[b][threadIdx.x];
        cnt[threadIdx.x] = s;
    }
    __syncthreads();
    if (threadIdx.x == 0){
        int off = 0;
        for (int l = T-1; l >= 0; --l){ g_cur[l] = off; off += cnt[l]; }
    }
}
__global__ void scatter_kernel(const int* __restrict__ elen){
    int i = blockIdx.x*blockDim.x + threadIdx.x;
    if (i >= E_TOT) return;
    int l = elen[i]-1;
    unsigned act = __activemask();
    unsigned mask = __match_any_sync(act, l);
    int lane = threadIdx.x & 31, leader = __ffs(mask)-1;
    int rank = __popc(mask & ((1u<<lane)-1));
    int base = 0;
    if (lane == leader) base = atomicAdd(&g_cur[l], __popc(mask));
    base = __shfl_sync(mask, base, leader);
    g_list[base+rank] = i;
}

// ---- one-shot weight prep ----
__global__ void prep_b_kernel(
    const float* __restrict__ Wih_e, const float* __restrict__ Whh_e,
    const float* __restrict__ bih_e, const float* __restrict__ bhh_e,
    const float* __restrict__ Wih_a, const float* __restrict__ Whh_a,
    const float* __restrict__ bih_a, const float* __restrict__ bhh_a,
    const float* __restrict__ t2v_w, const float* __restrict__ t2v_b,
    const float* __restrict__ t2v_w0, const float* __restrict__ t2v_b0)
{
    const int isA = blockIdx.x;
    const float* Wih = isA ? Wih_a : Wih_e;
    const float* Whh = isA ? Whh_a : Whh_e;
    const float* bih = isA ? bih_a : bih_e;
    const float* bhh = isA ? bhh_a : bhh_e;
    int j = threadIdx.x;
    int srcj = (j & 3)*64 + (j >> 2);
    __half* row = g_B[isA][j];
    const float* whr = Whh + srcj*64;
    #pragma unroll 4
    for (int k = 0; k < 64; k++) row[k] = __float2half_rn(__ldg(whr + k));
    const float* wir = Wih + srcj*16;
    #pragma unroll
    for (int kk = 0; kk < 16; kk++) row[64 + kk] = __float2half_rn(__ldg(wir + kk));
    #pragma unroll
    for (int kk = 80; kk < 88; kk++) row[kk] = __float2half_rn(0.f);
    g_bias[isA][j] = __ldg(bih + srcj) + __ldg(bhh + srcj);
    if (isA == 0 && j < 16){
        float v;
        if (j < 7) v = t2v_w[j]; else if (j < 14) v = t2v_b[j-7];
        else if (j == 14) v = t2v_w0[0]; else v = t2v_b0[0];
        g_tv[j] = v;
    }
}

// ---- x fill, split into 4 parts per edge (part = tid>>6, e = tid&63) ----
__device__ __forceinline__ void fill_x_part(char* smem, uint32_t ab, const float* sTv,
    const float* __restrict__ ef, const float* __restrict__ et, int eg, int t, int e, int part)
{
    if (part == 0){
        float4 v = __ldg((const float4*)(ef + ((size_t)eg*T + t)*8));
        *(uint32_t*)(smem + ael(ab, e, 64)) = pack_h2(v.x, v.y);
        *(uint32_t*)(smem + ael(ab, e, 66)) = pack_h2(v.z, v.w);
    } else if (part == 1){
        float4 v = __ldg((const float4*)(ef + ((size_t)eg*T + t)*8 + 4));
        *(uint32_t*)(smem + ael(ab, e, 68)) = pack_h2(v.x, v.y);
        *(uint32_t*)(smem + ael(ab, e, 70)) = pack_h2(v.z, v.w);
    } else if (part == 2){
        float tau = __ldg(et + (size_t)eg*T + t);
        float a0 = __sinf(fmaf(tau, sTv[0], sTv[7]));
        float a1 = __sinf(fmaf(tau, sTv[1], sTv[8]));
        float a2 = __sinf(fmaf(tau, sTv[2], sTv[9]));
        float a3 = __sinf(fmaf(tau, sTv[3], sTv[10]));
        *(uint32_t*)(smem + ael(ab, e, 72)) = pack_h2(a0, a1);
        *(uint32_t*)(smem + ael(ab, e, 74)) = pack_h2(a2, a3);
    } else {
        float tau = __ldg(et + (size_t)eg*T + t);
        float a4 = __sinf(fmaf(tau, sTv[4], sTv[11]));
        float a5 = __sinf(fmaf(tau, sTv[5], sTv[12]));
        float a6 = __sinf(fmaf(tau, sTv[6], sTv[13]));
        float a7 = fmaf(tau, sTv[14], sTv[15]);
        *(uint32_t*)(smem + ael(ab, e, 76)) = pack_h2(a4, a5);
        *(uint32_t*)(smem + ael(ab, e, 78)) = pack_h2(a6, a7);
    }
}

// ---- LSTM: 256 threads, 8 warps (n32), 64 edges, 2 CTAs/SM, pipelined A ----
__global__ void __launch_bounds__(256, 2) lstm_hmma_kernel(
    const float* __restrict__ ef, const float* __restrict__ et,
    const int*   __restrict__ elen)
{
    extern __shared__ char smem[];
    const uint32_t sb = smem_u32(smem);
    int*   sidx = (int*)(smem + OFF_SIDX);
    int*   slen = (int*)(smem + OFF_SLEN);
    float* sTv  = (float*)(smem + OFF_TV);
    int*   smax = (int*)(smem + OFF_SMAX);

    const int tid = threadIdx.x, wid = tid >> 5, lane = tid & 31;
    const int isA = blockIdx.y;
    __half* gout = isA ? g_aout : g_eout;

    if (tid == 0) *smax = 0;
    if (tid < 16) sTv[tid] = g_tv[tid];
    if (tid < TILE){
        int eg = g_list[blockIdx.x*TILE + tid];
        sidx[tid] = eg;
        int l = elen[eg];
        slen[tid] = l;
        atomicMax(smax, l);
    }
    {
        const float4* src = (const float4*)g_B[isA];
        float4* dst = (float4*)smem;
        #pragma unroll
        for (int i = 0; i < 11; i++) dst[tid + 256*i] = src[tid + 256*i];
    }
    __syncthreads();

    const int nw = wid;
    uint32_t Br[2][5][4];
    #pragma unroll
    for (int s = 0; s < 2; s++){
        int rowb = nw*32 + s*16 + ((lane >> 4) << 3) + (lane & 7);
        #pragma unroll
        for (int ks = 0; ks < 5; ks++){
            int chb = 2*ks + ((lane >> 3) & 1);
            ldm4(amat(sb + OFF_B, rowb, chb), Br[s][ks][0],Br[s][ks][1],Br[s][ks][2],Br[s][ks][3]);
        }
    }
    float bia[8];
    #pragma unroll
    for (int s = 0; s < 2; s++){
        int n0 = nw*32 + s*16 + 2*(lane & 3);
        bia[s*4+0] = __ldg(&g_bias[isA][n0]);
        bia[s*4+1] = __ldg(&g_bias[isA][n0+1]);
        bia[s*4+2] = __ldg(&g_bias[isA][n0+8]);
        bia[s*4+3] = __ldg(&g_bias[isA][n0+9]);
    }
    const int rc = (lane >> 2) + ((lane & 1) ? 8 : 0);
    int myg[4];
    uint32_t lens_pk = 0;
    #pragma unroll
    for (int i = 0; i < 4; i++){
        myg[i] = sidx[i*16 + rc];
        lens_pk |= (uint32_t)((slen[i*16 + rc] - 1) & 15) << (4*i);
    }
    __syncthreads();

    {
        float4 z = make_float4(0.f,0.f,0.f,0.f);
        float4* pa = (float4*)(smem + OFF_A);
        for (int i = tid; i < ABUF/16; i += 256) pa[i] = z;
    }
    __syncthreads();
    const int pe_e = sidx[tid & 63];
    const int ppart = tid >> 6;
    fill_x_part(smem, OFF_A, sTv, ef, et, pe_e, 0, tid & 63, ppart);
    __syncthreads();

    const int maxlen = *smax;
    const unsigned FULL = 0xffffffffu;
    const int ubase = nw*8;
    const __half2 hhalf = __float2half2_rn(0.5f);

    __half2 c2[8];
    #pragma unroll
    for (int i = 0; i < 8; i++) c2[i] = __float2half2_rn(0.f);

    for (int t = 0; t < maxlen; ++t){
        const int par = t & 1;
        const uint32_t aR = OFF_A + par*ABUF;
        const uint32_t aW = OFF_A + (par^1)*ABUF;

        if ((t+1) < maxlen)
            fill_x_part(smem, aW, sTv, ef, et, pe_e, t+1, tid & 63, ppart);

        uint32_t Afb[2][5][4];
        #pragma unroll
        for (int ks = 0; ks < 5; ks++){
            const int cc = 2*ks + (lane >> 4);
            ldm4(amat(sb + aR, (lane & 15), cc), Afb[0][ks][0],Afb[0][ks][1],Afb[0][ks][2],Afb[0][ks][3]);
        }
        #pragma unroll
        for (int i = 0; i < 4; i++){
            const int cur = i & 1, nxt = cur ^ 1;
            if (i < 3){
                const int r = (i+1)*16 + (lane & 15);
                #pragma unroll
                for (int ks = 0; ks < 5; ks++){
                    const int cc = 2*ks + (lane >> 4);
                    ldm4(amat(sb + aR, r, cc), Afb[nxt][ks][0],Afb[nxt][ks][1],Afb[nxt][ks][2],Afb[nxt][ks][3]);
                }
            }
            const bool last = (t == (int)((lens_pk >> (4*i)) & 15));
            const int edge = i*16 + rc;
            #pragma unroll
            for (int s = 0; s < 2; s++){
                float acc[8] = {bia[s*4+0], bia[s*4+1], bia[s*4+0], bia[s*4+1],
                                bia[s*4+2], bia[s*4+3], bia[s*4+2], bia[s*4+3]};
                #pragma unroll
                for (int ks = 0; ks < 5; ks++){
                    mma_fp16(acc,   Afb[cur][ks][0],Afb[cur][ks][1],Afb[cur][ks][2],Afb[cur][ks][3], Br[s][ks][0], Br[s][ks][1]);
                    mma_fp16(acc+4, Afb[cur][ks][0],Afb[cur][ks][1],Afb[cur][ks][2],Afb[cur][ks][3], Br[s][ks][2], Br[s][ks][3]);
                }
                float gi[2], gf[2], gg[2], go[2];
                #pragma unroll
                for (int f = 0; f < 2; f++){
                    float d0 = acc[4*f], d1 = acc[4*f+1], d2 = acc[4*f+2], d3 = acc[4*f+3];
                    float sx = (lane & 1) ? d0 : d2;
                    float sy = (lane & 1) ? d1 : d3;
                    float rx = __shfl_xor_sync(FULL, sx, 1);
                    float ry = __shfl_xor_sync(FULL, sy, 1);
                    if (lane & 1){ gi[f] = rx; gf[f] = ry; gg[f] = d2; go[f] = d3; }
                    else         { gi[f] = d0; gf[f] = d1; gg[f] = rx; go[f] = ry; }
                }
                __half2 I2 = __floats2half2_rn(gi[0], gi[1]);
                __half2 F2 = __floats2half2_rn(gf[0], gf[1]);
                __half2 G2 = __floats2half2_rn(gg[0], gg[1]);
                __half2 O2 = __floats2half2_rn(go[0], go[1]);
                __half2 iv = __hfma2(tanh2(__hmul2(I2, hhalf)), hhalf, hhalf);
                __half2 fv = __hfma2(tanh2(__hmul2(F2, hhalf)), hhalf, hhalf);
                __half2 ov = __hfma2(tanh2(__hmul2(O2, hhalf)), hhalf, hhalf);
                __half2 gv = tanh2(G2);
                const int ci = i*2 + s;
                c2[ci] = __hfma2(fv, c2[ci], __hmul2(iv, gv));
                __half2 h2 = __hmul2(ov, tanh2(c2[ci]));
                uint32_t h2u = *(uint32_t*)&h2;
                uint32_t hp = __shfl_xor_sync(FULL, h2u, 2);
                if (!(lane & 2)){
                    uint32_t lo = __byte_perm(h2u, hp, 0x5410);
                    uint32_t hi = __byte_perm(h2u, hp, 0x7632);
                    const int u0 = ubase + s*4;
                    *(uint32_t*)(smem + ael(aW, edge, u0))     = lo;
                    *(uint32_t*)(smem + ael(aW, edge, u0 + 2)) = hi;
                    if (last){
                        *(uint32_t*)(gout + (size_t)myg[i]*H + u0)     = lo;
                        *(uint32_t*)(gout + (size_t)myg[i]*H + u0 + 2) = hi;
                    }
                }
            }
        }
        __syncthreads();
    }
}

// ---- projections: P = nf@eW1^T, Q = nf[:8192]@nW1^T ----
__global__ void proj_kernel(const float* __restrict__ nf,
                            const float* __restrict__ eW, const float* __restrict__ nW)
{
    __shared__ float Wt[64*64];
    __shared__ float xs[16*64];
    const float* W = blockIdx.y ? nW : eW;
    float* out = blockIdx.y ? g_Q : g_P;
    int nrows = blockIdx.y ? N_DST : N_SRC;
    int r0 = blockIdx.x*16;
    if (r0 >= nrows) return;
    int tid = threadIdx.x;
    for (int idx = tid; idx < 4096; idx += 256){ int d = idx>>6, j = idx&63; Wt[idx] = W[j*128 + d]; }
    for (int idx = tid; idx < 1024; idx += 256) xs[idx] = nf[(size_t)r0*64 + idx];
    __syncthreads();
    for (int o = tid; o < 1024; o += 256){
        int ri = o>>6, j = o&63;
        float s = 0.f;
        #pragma unroll
        for (int d = 0; d < 64; d++) s = fmaf(xs[ri*64+d], Wt[d*64+j], s);
        out[(size_t)(r0+ri)*64 + j] = s;
    }
}

// ---- fused edge epilogue + per-dst sparsemax/aggregate/final MLP ----
// block = 128 edges = 4 dst nodes; 256 threads
__global__ void __launch_bounds__(256) edgedst_kernel(
    const float* __restrict__ eW, const float* __restrict__ eb,
    const float* __restrict__ attn, const int* __restrict__ esrc,
    const float* __restrict__ nW, const float* __restrict__ nb,
    float* __restrict__ out)
{
    extern __shared__ char smem[];
    __half* eo   = (__half*)(smem + FO_EO);
    __half* w2   = (__half*)(smem + FO_W2);
    float*  ms   = (float*)(smem + FO_MS);
    float*  nW2t = (float*)(smem + FO_NW2);
    float*  att  = (float*)(smem + FO_ATT);
    float*  bsh  = (float*)(smem + FO_BSH);
    float*  as   = (float*)(smem + FO_AS);
    float*  alp  = (float*)(smem + FO_AL);
    float*  hns  = (float*)(smem + FO_HNS);
    const uint32_t eob = smem_u32(eo), w2b = smem_u32(w2);
    int tid = threadIdx.x, wid = tid >> 5, lane = tid & 31;
    size_t e0 = (size_t)blockIdx.x*128;
    const unsigned FULL = 0xffffffffu;

    for (int idx = tid; idx < 4096; idx += 256){
        int row = idx >> 5, cp = idx & 31;
        *(uint32_t*)&eo[row*72 + cp*2] = *(const uint32_t*)&g_eout[(e0 + row)*64 + cp*2];
    }
    for (int idx = tid; idx < 2048; idx += 256){
        int j = idx >> 5, cp = idx & 31;
        *(uint32_t*)&w2[j*72 + cp*2] = pack_h2(eW[j*128 + 64 + cp*2], eW[j*128 + 64 + cp*2 + 1]);
    }
    for (int idx = tid; idx < 4096; idx += 256){
        int d = idx >> 6, j = idx & 63;
        nW2t[idx] = nW[j*128 + 64 + d];
    }
    if (tid < 64){ att[tid] = attn[tid]; bsh[tid] = eb[tid]; }
    __syncthreads();

    // m = relu(P[src] + e_out@W2^T + b) -> smem (fp32, stride 66)
    uint32_t Af[4][4];
    #pragma unroll
    for (int ks = 0; ks < 4; ks++){
        uint32_t addr = eob + (uint32_t)(wid*16 + (lane & 15))*144u + (uint32_t)(2*ks + (lane >> 4))*16u;
        ldm4(addr, Af[ks][0],Af[ks][1],Af[ks][2],Af[ks][3]);
    }
    const int r0e = wid*16 + (lane >> 2);
    const int s0 = esrc[e0 + r0e];
    const int s1 = esrc[e0 + r0e + 8];

    #pragma unroll
    for (int ng = 0; ng < 4; ng++){
        float acc[8] = {0.f,0.f,0.f,0.f,0.f,0.f,0.f,0.f};
        #pragma unroll
        for (int ks = 0; ks < 4; ks++){
            int rowb = ng*16 + ((lane >> 4) << 3) + (lane & 7);
            int chb  = 2*ks + ((lane >> 3) & 1);
            uint32_t b0,b1,b2,b3;
            ldm4(w2b + (uint32_t)rowb*144u + (uint32_t)chb*16u, b0,b1,b2,b3);
            mma_fp16(acc,   Af[ks][0],Af[ks][1],Af[ks][2],Af[ks][3], b0, b1);
            mma_fp16(acc+4, Af[ks][0],Af[ks][1],Af[ks][2],Af[ks][3], b2, b3);
        }
        const int c0 = ng*16 + 2*(lane & 3);
        float2 p00 = *(const float2*)(g_P + (size_t)s0*64 + c0);
        float2 p01 = *(const float2*)(g_P + (size_t)s0*64 + c0 + 8);
        float2 p10 = *(const float2*)(g_P + (size_t)s1*64 + c0);
        float2 p11 = *(const float2*)(g_P + (size_t)s1*64 + c0 + 8);
        float b0v = bsh[c0], b1v = bsh[c0+1], b2v = bsh[c0+8], b3v = bsh[c0+9];
        ms[r0e*66 + c0]       = fmaxf(acc[0]+p00.x+b0v, 0.f);
        ms[r0e*66 + c0 + 1]   = fmaxf(acc[1]+p00.y+b1v, 0.f);
        ms[(r0e+8)*66 + c0]   = fmaxf(acc[2]+p10.x+b0v, 0.f);
        ms[(r0e+8)*66 + c0+1] = fmaxf(acc[3]+p10.y+b1v, 0.f);
        ms[r0e*66 + c0 + 8]   = fmaxf(acc[4]+p01.x+b2v, 0.f);
        ms[r0e*66 + c0 + 9]   = fmaxf(acc[5]+p01.y+b3v, 0.f);
        ms[(r0e+8)*66 + c0+8] = fmaxf(acc[6]+p11.x+b2v, 0.f);
        ms[(r0e+8)*66 + c0+9] = fmaxf(acc[7]+p11.y+b3v, 0.f);
    }

    // attention logits
    if (tid < 128){
        size_t e = e0 + tid;
        const __half2* ar = (const __half2*)&g_aout[e*64];
        float s = 0.f;
        #pragma unroll
        for (int d = 0; d < 32; d++){
            float2 v = __half22float2(ar[d]);
            s += v.x*att[2*d] + v.y*att[2*d+1];
        }
        as[tid] = (s > 0.f) ? s : 0.01f*s;
    }
    __syncthreads();

    // sparsemax per dst (warps 0-3)
    if (wid < 4){
        float av = as[wid*32 + lane];
        float mx = av;
        #pragma unroll
        for (int o = 16; o > 0; o >>= 1) mx = fmaxf(mx, __shfl_xor_sync(FULL, mx, o));
        float z = av - mx;
        float v = z;
        #pragma unroll
        for (int k = 2; k <= 32; k <<= 1){
            #pragma unroll
            for (int j = k>>1; j > 0; j >>= 1){
                float o = __shfl_xor_sync(FULL, v, j);
                bool lower = (lane & j) == 0, asc = (lane & k) != 0;
                v = (lower == asc) ? fminf(v, o) : fmaxf(v, o);
            }
        }
        float cs = v;
        #pragma unroll
        for (int o = 1; o < 32; o <<= 1){
            float t = __shfl_up_sync(FULL, cs, o);
            if (lane >= o) cs += t;
        }
        float r = (float)(lane+1);
        bool gt = (1.f + r*v) > cs;
        float kk = gt ? r : 0.f, sz = gt ? v : 0.f;
        #pragma unroll
        for (int o = 16; o > 0; o >>= 1){
            kk = fmaxf(kk, __shfl_xor_sync(FULL, kk, o));
            sz += __shfl_xor_sync(FULL, sz, o);
        }
        alp[wid*32 + lane] = fmaxf(z - (sz - 1.f)/kk, 0.f);
    }
    __syncthreads();

    // h_neigh: thread (dstl = tid>>6, dim = tid&63)
    const int dstl = tid >> 6, dim = tid & 63;
    {
        float hn = 0.f;
        const float* al = alp + dstl*32;
        const float* mrow = ms + dstl*32*66 + dim;
        #pragma unroll 8
        for (int k = 0; k < 32; k++)
            hn = fmaf(al[k], mrow[k*66], hn);
        hns[dstl*64 + dim] = hn;
    }
    __syncthreads();

    // final MLP
    {
        int dst = blockIdx.x*4 + dstl;
        float o = bsh[0];   // placeholder overwritten below
        o = nb[dim] + g_Q[(size_t)dst*64 + dim];
        const float* hrow = hns + dstl*64;
        #pragma unroll 8
        for (int d = 0; d < 64; d++)
            o = fmaf(hrow[d], nW2t[d*64 + dim], o);
        out[(size_t)dst*64 + dim] = fmaxf(o, 0.f);
    }
}

// ---- launcher ----
extern "C" void kernel_launch(void* const* d_in, const int* in_sizes, int n_in,
                              void* d_out, int out_size)
{
    int iNF,iEF,iET,iLEN,iSRC,iT2W,iT2B,iT2W0,iT2B0;
    int iEWih,iEWhh,iEBih,iEBhh,iAWih,iAWhh,iABih,iABhh,iATT,iEOW,iEOB,iNW,iNB;
    if (in_sizes[3] == E_TOT){
        iNF=0;iEF=1;iET=2;iLEN=3;iSRC=4;iT2W=5;iT2B=6;iT2W0=7;iT2B0=8;
        iEWih=9;iEWhh=10;iEBih=11;iEBhh=12;iAWih=13;iAWhh=14;iABih=15;iABhh=16;
        iATT=17;iEOW=18;iEOB=19;iNW=20;iNB=21;
    } else {
        iNF=0;iEF=1;iET=2;iT2W=3;iT2B=4;iT2W0=5;iT2B0=6;
        iEWih=7;iEWhh=8;iEBih=9;iEBhh=10;iAWih=11;iAWhh=12;iABih=13;iABhh=14;
        iATT=15;iEOW=16;iEOB=17;iNW=18;iNB=19;iLEN=20;iSRC=21;
    }
    const float* nf   = (const float*)d_in[iNF];
    const float* ef   = (const float*)d_in[iEF];
    const float* et   = (const float*)d_in[iET];
    const int*   elen = (const int*)  d_in[iLEN];
    const int*   esrc = (const int*)  d_in[iSRC];
    float* out = (float*)d_out;

    cudaFuncSetAttribute(lstm_hmma_kernel, cudaFuncAttributeMaxDynamicSharedMemorySize, LSTM_SMEM);
    cudaFuncSetAttribute(edgedst_kernel, cudaFuncAttributeMaxDynamicSharedMemorySize, FUSED_SMEM);

    hist_part_kernel<<<128, 256>>>(elen);
    prep_b_kernel<<<2, 256>>>(
        (const float*)d_in[iEWih], (const float*)d_in[iEWhh],
        (const float*)d_in[iEBih], (const float*)d_in[iEBhh],
        (const float*)d_in[iAWih], (const float*)d_in[iAWhh],
        (const float*)d_in[iABih], (const float*)d_in[iABhh],
        (const float*)d_in[iT2W], (const float*)d_in[iT2B],
        (const float*)d_in[iT2W0], (const float*)d_in[iT2B0]);
    scan2_kernel<<<1, 256>>>();
    scatter_kernel<<<E_TOT/256, 256>>>(elen);

    lstm_hmma_kernel<<<dim3(E_TOT/TILE, 2), 256, LSTM_SMEM>>>(ef, et, elen);

    proj_kernel<<<dim3(N_SRC/16, 2), 256>>>(nf, (const float*)d_in[iEOW], (const float*)d_in[iNW]);
    edgedst_kernel<<<E_TOT/128, 256, FUSED_SMEM>>>(
        (const float*)d_in[iEOW], (const float*)d_in[iEOB],
        (const float*)d_in[iATT], esrc,
        (const float*)d_in[iNW], (const float*)d_in[iNB], out);
}

// round 15
// speedup vs baseline: 1.0307x; 1.0307x over previous
#include <cuda_runtime.h>
#include <cuda_fp16.h>
#include <math.h>
#include <stdint.h>

#define N_SRC 16384
#define N_DST 8192
#define KNB 32
#define E_TOT (N_DST*KNB)
#define T 16
#define H 64
#define TILE 64

// ---- scratch ----
__device__ __half g_eout[(size_t)E_TOT*H];
__device__ __half g_aout[(size_t)E_TOT*H];
__device__ __half g_m[(size_t)E_TOT*H];
__device__ float g_a[E_TOT];
__device__ float g_P[N_SRC*H];
__device__ float g_Q[N_DST*H];
__device__ int   g_list[E_TOT];
__device__ int   g_part[128][16];
__device__ int   g_cur[T];
__device__ __half g_B[2][256][88];
__device__ float  g_bias[2][256];
__device__ float  g_tv[16];

// ---- LSTM smem byte map (per CTA) ----
#define OFF_B    0
#define OFF_A    0
#define ABUF     11264
#define OFF_SIDX 45056
#define OFF_SLEN 45312
#define OFF_TV   45568
#define OFF_SMAX 45632
#define LSTM_SMEM 45696

__device__ __forceinline__ uint32_t smem_u32(const void* p){
    uint32_t a; asm("{ .reg .u64 t; cvta.to.shared.u64 t, %1; cvt.u32.u64 %0, t; }":"=r"(a):"l"(p)); return a;
}
__device__ __forceinline__ uint32_t amat(uint32_t base, int row, int ch){
    return base + (uint32_t)row*176u + ((uint32_t)ch << 4);
}
__device__ __forceinline__ uint32_t ael(uint32_t base, int row, int k){
    return base + (uint32_t)row*176u + ((uint32_t)k << 1);
}
__device__ __forceinline__ void ldm4(uint32_t addr, uint32_t &r0, uint32_t &r1, uint32_t &r2, uint32_t &r3){
    asm volatile("ldmatrix.sync.aligned.m8n8.x4.shared.b16 {%0,%1,%2,%3}, [%4];"
        : "=r"(r0),"=r"(r1),"=r"(r2),"=r"(r3) : "r"(addr));
}
__device__ __forceinline__ void mma_fp16(float* c, uint32_t a0,uint32_t a1,uint32_t a2,uint32_t a3,
                                         uint32_t b0, uint32_t b1){
    asm volatile("mma.sync.aligned.m16n8k16.row.col.f32.f16.f16.f32 "
        "{%0,%1,%2,%3}, {%4,%5,%6,%7}, {%8,%9}, {%0,%1,%2,%3};"
        : "+f"(c[0]),"+f"(c[1]),"+f"(c[2]),"+f"(c[3])
        : "r"(a0),"r"(a1),"r"(a2),"r"(a3),"r"(b0),"r"(b1));
}
__device__ __forceinline__ __half2 tanh2(__half2 x){
    uint32_t xi = *(uint32_t*)&x, yi;
    asm("tanh.approx.f16x2 %0, %1;" : "=r"(yi) : "r"(xi));
    return *(__half2*)&yi;
}
__device__ __forceinline__ uint32_t pack_h2(float a, float b){
    __half2 v; v.x = __float2half_rn(a); v.y = __float2half_rn(b);
    return *(uint32_t*)&v;
}

// ---- bucketing ----
__global__ void hist_part_kernel(const int* __restrict__ elen){
    __shared__ int h[T];
    if (threadIdx.x < T) h[threadIdx.x] = 0;
    __syncthreads();
    int base = blockIdx.x * 2048;
    for (int i = threadIdx.x; i < 2048; i += 256) atomicAdd(&h[elen[base + i] - 1], 1);
    __syncthreads();
    if (threadIdx.x < T) g_part[blockIdx.x][threadIdx.x] = h[threadIdx.x];
}
__global__ void scan2_kernel(){
    __shared__ int cnt[T];
    if (threadIdx.x < T){
        int s = 0;
        for (int b = 0; b < 128; b++) s += g_part[b][threadIdx.x];
        cnt[threadIdx.x] = s;
    }
    __syncthreads();
    if (threadIdx.x == 0){
        int off = 0;
        for (int l = T-1; l >= 0; --l){ g_cur[l] = off; off += cnt[l]; }
    }
}
__global__ void scatter_kernel(const int* __restrict__ elen){
    int i = blockIdx.x*blockDim.x + threadIdx.x;
    if (i >= E_TOT) return;
    int l = elen[i]-1;
    unsigned act = __activemask();
    unsigned mask = __match_any_sync(act, l);
    int lane = threadIdx.x & 31, leader = __ffs(mask)-1;
    int rank = __popc(mask & ((1u<<lane)-1));
    int base = 0;
    if (lane == leader) base = atomicAdd(&g_cur[l], __popc(mask));
    base = __shfl_sync(mask, base, leader);
    g_list[base+rank] = i;
}

// ---- one-shot weight prep ----
__global__ void prep_b_kernel(
    const float* __restrict__ Wih_e, const float* __restrict__ Whh_e,
    const float* __restrict__ bih_e, const float* __restrict__ bhh_e,
    const float* __restrict__ Wih_a, const float* __restrict__ Whh_a,
    const float* __restrict__ bih_a, const float* __restrict__ bhh_a,
    const float* __restrict__ t2v_w, const float* __restrict__ t2v_b,
    const float* __restrict__ t2v_w0, const float* __restrict__ t2v_b0)
{
    const int isA = blockIdx.x;
    const float* Wih = isA ? Wih_a : Wih_e;
    const float* Whh = isA ? Whh_a : Whh_e;
    const float* bih = isA ? bih_a : bih_e;
    const float* bhh = isA ? bhh_a : bhh_e;
    int j = threadIdx.x;
    int srcj = (j & 3)*64 + (j >> 2);
    __half* row = g_B[isA][j];
    const float* whr = Whh + srcj*64;
    #pragma unroll 4
    for (int k = 0; k < 64; k++) row[k] = __float2half_rn(__ldg(whr + k));
    const float* wir = Wih + srcj*16;
    #pragma unroll
    for (int kk = 0; kk < 16; kk++) row[64 + kk] = __float2half_rn(__ldg(wir + kk));
    #pragma unroll
    for (int kk = 80; kk < 88; kk++) row[kk] = __float2half_rn(0.f);
    g_bias[isA][j] = __ldg(bih + srcj) + __ldg(bhh + srcj);
    if (isA == 0 && j < 16){
        float v;
        if (j < 7) v = t2v_w[j]; else if (j < 14) v = t2v_b[j-7];
        else if (j == 14) v = t2v_w0[0]; else v = t2v_b0[0];
        g_tv[j] = v;
    }
}

// ---- x fill, split into 4 parts per edge (part = tid>>6, e = tid&63) ----
__device__ __forceinline__ void fill_x_part(char* smem, uint32_t ab, const float* sTv,
    const float* __restrict__ ef, const float* __restrict__ et, int eg, int t, int e, int part)
{
    if (part == 0){
        float4 v = __ldg((const float4*)(ef + ((size_t)eg*T + t)*8));
        *(uint32_t*)(smem + ael(ab, e, 64)) = pack_h2(v.x, v.y);
        *(uint32_t*)(smem + ael(ab, e, 66)) = pack_h2(v.z, v.w);
    } else if (part == 1){
        float4 v = __ldg((const float4*)(ef + ((size_t)eg*T + t)*8 + 4));
        *(uint32_t*)(smem + ael(ab, e, 68)) = pack_h2(v.x, v.y);
        *(uint32_t*)(smem + ael(ab, e, 70)) = pack_h2(v.z, v.w);
    } else if (part == 2){
        float tau = __ldg(et + (size_t)eg*T + t);
        float a0 = __sinf(fmaf(tau, sTv[0], sTv[7]));
        float a1 = __sinf(fmaf(tau, sTv[1], sTv[8]));
        float a2 = __sinf(fmaf(tau, sTv[2], sTv[9]));
        float a3 = __sinf(fmaf(tau, sTv[3], sTv[10]));
        *(uint32_t*)(smem + ael(ab, e, 72)) = pack_h2(a0, a1);
        *(uint32_t*)(smem + ael(ab, e, 74)) = pack_h2(a2, a3);
    } else {
        float tau = __ldg(et + (size_t)eg*T + t);
        float a4 = __sinf(fmaf(tau, sTv[4], sTv[11]));
        float a5 = __sinf(fmaf(tau, sTv[5], sTv[12]));
        float a6 = __sinf(fmaf(tau, sTv[6], sTv[13]));
        float a7 = fmaf(tau, sTv[14], sTv[15]);
        *(uint32_t*)(smem + ael(ab, e, 76)) = pack_h2(a4, a5);
        *(uint32_t*)(smem + ael(ab, e, 78)) = pack_h2(a6, a7);
    }
}

// ---- LSTM: 256 threads, 8 warps (n32), 64 edges, 2 CTAs/SM, pipelined A,
//      t=0 skips the dead h-part (h==0) ----
__global__ void __launch_bounds__(256, 2) lstm_hmma_kernel(
    const float* __restrict__ ef, const float* __restrict__ et,
    const int*   __restrict__ elen)
{
    extern __shared__ char smem[];
    const uint32_t sb = smem_u32(smem);
    int*   sidx = (int*)(smem + OFF_SIDX);
    int*   slen = (int*)(smem + OFF_SLEN);
    float* sTv  = (float*)(smem + OFF_TV);
    int*   smax = (int*)(smem + OFF_SMAX);

    const int tid = threadIdx.x, wid = tid >> 5, lane = tid & 31;
    const int isA = blockIdx.y;
    __half* gout = isA ? g_aout : g_eout;

    if (tid == 0) *smax = 0;
    if (tid < 16) sTv[tid] = g_tv[tid];
    if (tid < TILE){
        int eg = g_list[blockIdx.x*TILE + tid];
        sidx[tid] = eg;
        int l = elen[eg];
        slen[tid] = l;
        atomicMax(smax, l);
    }
    {
        const float4* src = (const float4*)g_B[isA];
        float4* dst = (float4*)smem;
        #pragma unroll
        for (int i = 0; i < 11; i++) dst[tid + 256*i] = src[tid + 256*i];
    }
    __syncthreads();

    const int nw = wid;
    uint32_t Br[2][5][4];
    #pragma unroll
    for (int s = 0; s < 2; s++){
        int rowb = nw*32 + s*16 + ((lane >> 4) << 3) + (lane & 7);
        #pragma unroll
        for (int ks = 0; ks < 5; ks++){
            int chb = 2*ks + ((lane >> 3) & 1);
            ldm4(amat(sb + OFF_B, rowb, chb), Br[s][ks][0],Br[s][ks][1],Br[s][ks][2],Br[s][ks][3]);
        }
    }
    float bia[8];
    #pragma unroll
    for (int s = 0; s < 2; s++){
        int n0 = nw*32 + s*16 + 2*(lane & 3);
        bia[s*4+0] = __ldg(&g_bias[isA][n0]);
        bia[s*4+1] = __ldg(&g_bias[isA][n0+1]);
        bia[s*4+2] = __ldg(&g_bias[isA][n0+8]);
        bia[s*4+3] = __ldg(&g_bias[isA][n0+9]);
    }
    const int rc = (lane >> 2) + ((lane & 1) ? 8 : 0);
    int myg[4];
    uint32_t lens_pk = 0;
    #pragma unroll
    for (int i = 0; i < 4; i++){
        myg[i] = sidx[i*16 + rc];
        lens_pk |= (uint32_t)((slen[i*16 + rc] - 1) & 15) << (4*i);
    }
    __syncthreads();   // B smem reads done; A region may overwrite

    const int pe_e = sidx[tid & 63];
    const int ppart = tid >> 6;
    fill_x_part(smem, OFF_A, sTv, ef, et, pe_e, 0, tid & 63, ppart);
    __syncthreads();

    const int maxlen = *smax;
    const unsigned FULL = 0xffffffffu;
    const int ubase = nw*8;
    const __half2 hhalf = __float2half2_rn(0.5f);

    __half2 c2[8];
    #pragma unroll
    for (int i = 0; i < 8; i++) c2[i] = __float2half2_rn(0.f);

    for (int t = 0; t < maxlen; ++t){
        const int par = t & 1;
        const uint32_t aR = OFF_A + par*ABUF;
        const uint32_t aW = OFF_A + (par^1)*ABUF;
        const bool skiph = (t == 0);    // h==0 at t=0: skip dead h k-steps

        if ((t+1) < maxlen)
            fill_x_part(smem, aW, sTv, ef, et, pe_e, t+1, tid & 63, ppart);

        uint32_t Afb[2][5][4];
        #pragma unroll
        for (int ks = 0; ks < 5; ks++){
            if (skiph && ks < 4) continue;
            const int cc = 2*ks + (lane >> 4);
            ldm4(amat(sb + aR, (lane & 15), cc), Afb[0][ks][0],Afb[0][ks][1],Afb[0][ks][2],Afb[0][ks][3]);
        }
        #pragma unroll
        for (int i = 0; i < 4; i++){
            const int cur = i & 1, nxt = cur ^ 1;
            if (i < 3){
                const int r = (i+1)*16 + (lane & 15);
                #pragma unroll
                for (int ks = 0; ks < 5; ks++){
                    if (skiph && ks < 4) continue;
                    const int cc = 2*ks + (lane >> 4);
                    ldm4(amat(sb + aR, r, cc), Afb[nxt][ks][0],Afb[nxt][ks][1],Afb[nxt][ks][2],Afb[nxt][ks][3]);
                }
            }
            const bool last = (t == (int)((lens_pk >> (4*i)) & 15));
            const int edge = i*16 + rc;
            #pragma unroll
            for (int s = 0; s < 2; s++){
                float acc[8] = {bia[s*4+0], bia[s*4+1], bia[s*4+0], bia[s*4+1],
                                bia[s*4+2], bia[s*4+3], bia[s*4+2], bia[s*4+3]};
                #pragma unroll
                for (int ks = 0; ks < 5; ks++){
                    if (skiph && ks < 4) continue;
                    mma_fp16(acc,   Afb[cur][ks][0],Afb[cur][ks][1],Afb[cur][ks][2],Afb[cur][ks][3], Br[s][ks][0], Br[s][ks][1]);
                    mma_fp16(acc+4, Afb[cur][ks][0],Afb[cur][ks][1],Afb[cur][ks][2],Afb[cur][ks][3], Br[s][ks][2], Br[s][ks][3]);
                }
                float gi[2], gf[2], gg[2], go[2];
                #pragma unroll
                for (int f = 0; f < 2; f++){
                    float d0 = acc[4*f], d1 = acc[4*f+1], d2 = acc[4*f+2], d3 = acc[4*f+3];
                    float sx = (lane & 1) ? d0 : d2;
                    float sy = (lane & 1) ? d1 : d3;
                    float rx = __shfl_xor_sync(FULL, sx, 1);
                    float ry = __shfl_xor_sync(FULL, sy, 1);
                    if (lane & 1){ gi[f] = rx; gf[f] = ry; gg[f] = d2; go[f] = d3; }
                    else         { gi[f] = d0; gf[f] = d1; gg[f] = rx; go[f] = ry; }
                }
                __half2 I2 = __floats2half2_rn(gi[0], gi[1]);
                __half2 F2 = __floats2half2_rn(gf[0], gf[1]);
                __half2 G2 = __floats2half2_rn(gg[0], gg[1]);
                __half2 O2 = __floats2half2_rn(go[0], go[1]);
                __half2 iv = __hfma2(tanh2(__hmul2(I2, hhalf)), hhalf, hhalf);
                __half2 fv = __hfma2(tanh2(__hmul2(F2, hhalf)), hhalf, hhalf);
                __half2 ov = __hfma2(tanh2(__hmul2(O2, hhalf)), hhalf, hhalf);
                __half2 gv = tanh2(G2);
                const int ci = i*2 + s;
                c2[ci] = __hfma2(fv, c2[ci], __hmul2(iv, gv));
                __half2 h2 = __hmul2(ov, tanh2(c2[ci]));
                uint32_t h2u = *(uint32_t*)&h2;
                uint32_t hp = __shfl_xor_sync(FULL, h2u, 2);
                if (!(lane & 2)){
                    uint32_t lo = __byte_perm(h2u, hp, 0x5410);
                    uint32_t hi = __byte_perm(h2u, hp, 0x7632);
                    const int u0 = ubase + s*4;
                    *(uint32_t*)(smem + ael(aW, edge, u0))     = lo;
                    *(uint32_t*)(smem + ael(aW, edge, u0 + 2)) = hi;
                    if (last){
                        *(uint32_t*)(gout + (size_t)myg[i]*H + u0)     = lo;
                        *(uint32_t*)(gout + (size_t)myg[i]*H + u0 + 2) = hi;
                    }
                }
            }
        }
        __syncthreads();
    }
}

// ---- projections: P = nf@eW1^T, Q = nf[:8192]@nW1^T ----
__global__ void proj_kernel(const float* __restrict__ nf,
                            const float* __restrict__ eW, const float* __restrict__ nW)
{
    __shared__ float Wt[64*64];
    __shared__ float xs[16*64];
    const float* W = blockIdx.y ? nW : eW;
    float* out = blockIdx.y ? g_Q : g_P;
    int nrows = blockIdx.y ? N_DST : N_SRC;
    int r0 = blockIdx.x*16;
    if (r0 >= nrows) return;
    int tid = threadIdx.x;
    for (int idx = tid; idx < 4096; idx += 256){ int d = idx>>6, j = idx&63; Wt[idx] = W[j*128 + d]; }
    for (int idx = tid; idx < 1024; idx += 256) xs[idx] = nf[(size_t)r0*64 + idx];
    __syncthreads();
    for (int o = tid; o < 1024; o += 256){
        int ri = o>>6, j = o&63;
        float s = 0.f;
        #pragma unroll
        for (int d = 0; d < 64; d++) s = fmaf(xs[ri*64+d], Wt[d*64+j], s);
        out[(size_t)(r0+ri)*64 + j] = s;
    }
}

// ---- edge epilogue via HMMA: 128 edges/block, warp = m16 x n64 x k64 ----
__global__ void __launch_bounds__(256) edgem_kernel(
    const float* __restrict__ eW, const float* __restrict__ eb,
    const float* __restrict__ attn, const int* __restrict__ esrc)
{
    __shared__ __half eo[128*72];
    __shared__ __half w2[64*72];
    __shared__ float att[64], bsh[64];
    const uint32_t eob = smem_u32(eo), w2b = smem_u32(w2);
    int tid = threadIdx.x, wid = tid >> 5, lane = tid & 31;
    size_t e0 = (size_t)blockIdx.x*128;

    for (int idx = tid; idx < 4096; idx += 256){
        int row = idx >> 5, cp = idx & 31;
        *(uint32_t*)&eo[row*72 + cp*2] = *(const uint32_t*)&g_eout[(e0 + row)*64 + cp*2];
    }
    for (int idx = tid; idx < 2048; idx += 256){
        int j = idx >> 5, cp = idx & 31;
        *(uint32_t*)&w2[j*72 + cp*2] = pack_h2(eW[j*128 + 64 + cp*2], eW[j*128 + 64 + cp*2 + 1]);
    }
    if (tid < 64){ att[tid] = attn[tid]; bsh[tid] = eb[tid]; }
    __syncthreads();

    uint32_t Af[4][4];
    #pragma unroll
    for (int ks = 0; ks < 4; ks++){
        uint32_t addr = eob + (uint32_t)(wid*16 + (lane & 15))*144u + (uint32_t)(2*ks + (lane >> 4))*16u;
        ldm4(addr, Af[ks][0],Af[ks][1],Af[ks][2],Af[ks][3]);
    }
    const int r0e = wid*16 + (lane >> 2);
    const int s0 = esrc[e0 + r0e];
    const int s1 = esrc[e0 + r0e + 8];

    #pragma unroll
    for (int ng = 0; ng < 4; ng++){
        float acc[8] = {0.f,0.f,0.f,0.f,0.f,0.f,0.f,0.f};
        #pragma unroll
        for (int ks = 0; ks < 4; ks++){
            int rowb = ng*16 + ((lane >> 4) << 3) + (lane & 7);
            int chb  = 2*ks + ((lane >> 3) & 1);
            uint32_t b0,b1,b2,b3;
            ldm4(w2b + (uint32_t)rowb*144u + (uint32_t)chb*16u, b0,b1,b2,b3);
            mma_fp16(acc,   Af[ks][0],Af[ks][1],Af[ks][2],Af[ks][3], b0, b1);
            mma_fp16(acc+4, Af[ks][0],Af[ks][1],Af[ks][2],Af[ks][3], b2, b3);
        }
        const int c0 = ng*16 + 2*(lane & 3);
        float2 p00 = *(const float2*)(g_P + (size_t)s0*64 + c0);
        float2 p01 = *(const float2*)(g_P + (size_t)s0*64 + c0 + 8);
        float2 p10 = *(const float2*)(g_P + (size_t)s1*64 + c0);
        float2 p11 = *(const float2*)(g_P + (size_t)s1*64 + c0 + 8);
        float b0v = bsh[c0], b1v = bsh[c0+1], b2v = bsh[c0+8], b3v = bsh[c0+9];
        *(uint32_t*)&g_m[(e0 + r0e)*64 + c0] =
            pack_h2(fmaxf(acc[0]+p00.x+b0v, 0.f), fmaxf(acc[1]+p00.y+b1v, 0.f));
        *(uint32_t*)&g_m[(e0 + r0e + 8)*64 + c0] =
            pack_h2(fmaxf(acc[2]+p10.x+b0v, 0.f), fmaxf(acc[3]+p10.y+b1v, 0.f));
        *(uint32_t*)&g_m[(e0 + r0e)*64 + c0 + 8] =
            pack_h2(fmaxf(acc[4]+p01.x+b2v, 0.f), fmaxf(acc[5]+p01.y+b3v, 0.f));
        *(uint32_t*)&g_m[(e0 + r0e + 8)*64 + c0 + 8] =
            pack_h2(fmaxf(acc[6]+p11.x+b2v, 0.f), fmaxf(acc[7]+p11.y+b3v, 0.f));
    }

    if (tid < 128){
        size_t e = e0 + tid;
        const __half2* ar = (const __half2*)&g_aout[e*64];
        float s = 0.f;
        #pragma unroll
        for (int d = 0; d < 32; d++){
            float2 v = __half22float2(ar[d]);
            s += v.x*att[2*d] + v.y*att[2*d+1];
        }
        g_a[e] = (s > 0.f) ? s : 0.01f*s;
    }
}

// ---- per-dst: sparsemax + aggregate + final MLP ----
__global__ void __launch_bounds__(256) dst_kernel(
    const float* __restrict__ nW, const float* __restrict__ nb, float* __restrict__ out)
{
    __shared__ float nW2t[64*64];
    __shared__ float nbs[64];
    __shared__ float hns[8][64];
    int tid = threadIdx.x;
    for (int idx = tid; idx < 4096; idx += 256){ int d = idx>>6, j = idx&63; nW2t[idx] = nW[j*128 + 64 + d]; }
    if (tid < 64) nbs[tid] = nb[tid];
    __syncthreads();
    int w = tid>>5, lane = tid&31;
    int dst = blockIdx.x*8 + w;
    const unsigned FULL = 0xffffffffu;

    float av = g_a[(size_t)dst*KNB + lane];
    float mx = av;
    #pragma unroll
    for (int o = 16; o > 0; o >>= 1) mx = fmaxf(mx, __shfl_xor_sync(FULL, mx, o));
    float z = av - mx;
    float v = z;
    #pragma unroll
    for (int k = 2; k <= 32; k <<= 1){
        #pragma unroll
        for (int j = k>>1; j > 0; j >>= 1){
            float o = __shfl_xor_sync(FULL, v, j);
            bool lower = (lane & j) == 0, asc = (lane & k) != 0;
            v = (lower == asc) ? fminf(v, o) : fmaxf(v, o);
        }
    }
    float cs = v;
    #pragma unroll
    for (int o = 1; o < 32; o <<= 1){
        float t = __shfl_up_sync(FULL, cs, o);
        if (lane >= o) cs += t;
    }
    float r = (float)(lane+1);
    bool gt = (1.f + r*v) > cs;
    float kk = gt ? r : 0.f, sz = gt ? v : 0.f;
    #pragma unroll
    for (int o = 16; o > 0; o >>= 1){
        kk = fmaxf(kk, __shfl_xor_sync(FULL, kk, o));
        sz += __shfl_xor_sync(FULL, sz, o);
    }
    float alpha = fmaxf(z - (sz - 1.f)/kk, 0.f);

    float hn0 = 0.f, hn1 = 0.f;
    #pragma unroll
    for (int k2 = 0; k2 < 32; k2++){
        float al = __shfl_sync(FULL, alpha, k2);
        if (al > 0.f){
            __half2 mv2 = *(const __half2*)&g_m[((size_t)dst*KNB + k2)*64 + lane*2];
            float2 mv = __half22float2(mv2);
            hn0 = fmaf(al, mv.x, hn0);
            hn1 = fmaf(al, mv.y, hn1);
        }
    }
    hns[w][lane*2] = hn0; hns[w][lane*2+1] = hn1;
    __syncwarp();
    float o0 = nbs[lane*2]   + g_Q[(size_t)dst*64 + lane*2];
    float o1 = nbs[lane*2+1] + g_Q[(size_t)dst*64 + lane*2+1];
    #pragma unroll 8
    for (int d = 0; d < 64; d++){
        float h = hns[w][d];
        float2 wv = *(const float2*)(nW2t + d*64 + lane*2);
        o0 = fmaf(h, wv.x, o0);
        o1 = fmaf(h, wv.y, o1);
    }
    size_t ob = (size_t)dst*64 + lane*2;
    out[ob] = fmaxf(o0, 0.f);
    out[ob+1] = fmaxf(o1, 0.f);
}

// ---- launcher ----
extern "C" void kernel_launch(void* const* d_in, const int* in_sizes, int n_in,
                              void* d_out, int out_size)
{
    int iNF,iEF,iET,iLEN,iSRC,iT2W,iT2B,iT2W0,iT2B0;
    int iEWih,iEWhh,iEBih,iEBhh,iAWih,iAWhh,iABih,iABhh,iATT,iEOW,iEOB,iNW,iNB;
    if (in_sizes[3] == E_TOT){
        iNF=0;iEF=1;iET=2;iLEN=3;iSRC=4;iT2W=5;iT2B=6;iT2W0=7;iT2B0=8;
        iEWih=9;iEWhh=10;iEBih=11;iEBhh=12;iAWih=13;iAWhh=14;iABih=15;iABhh=16;
        iATT=17;iEOW=18;iEOB=19;iNW=20;iNB=21;
    } else {
        iNF=0;iEF=1;iET=2;iT2W=3;iT2B=4;iT2W0=5;iT2B0=6;
        iEWih=7;iEWhh=8;iEBih=9;iEBhh=10;iAWih=11;iAWhh=12;iABih=13;iABhh=14;
        iATT=15;iEOW=16;iEOB=17;iNW=18;iNB=19;iLEN=20;iSRC=21;
    }
    const float* nf   = (const float*)d_in[iNF];
    const float* ef   = (const float*)d_in[iEF];
    const float* et   = (const float*)d_in[iET];
    const int*   elen = (const int*)  d_in[iLEN];
    const int*   esrc = (const int*)  d_in[iSRC];
    float* out = (float*)d_out;

    cudaFuncSetAttribute(lstm_hmma_kernel, cudaFuncAttributeMaxDynamicSharedMemorySize, LSTM_SMEM);

    hist_part_kernel<<<128, 256>>>(elen);
    prep_b_kernel<<<2, 256>>>(
        (const float*)d_in[iEWih], (const float*)d_in[iEWhh],
        (const float*)d_in[iEBih], (const float*)d_in[iEBhh],
        (const float*)d_in[iAWih], (const float*)d_in[iAWhh],
        (const float*)d_in[iABih], (const float*)d_in[iABhh],
        (const float*)d_in[iT2W], (const float*)d_in[iT2B],
        (const float*)d_in[iT2W0], (const float*)d_in[iT2B0]);
    scan2_kernel<<<1, 256>>>();
    scatter_kernel<<<E_TOT/256, 256>>>(elen);

    lstm_hmma_kernel<<<dim3(E_TOT/TILE, 2), 256, LSTM_SMEM>>>(ef, et, elen);

    proj_kernel<<<dim3(N_SRC/16, 2), 256>>>(nf, (const float*)d_in[iEOW], (const float*)d_in[iNW]);
    edgem_kernel<<<E_TOT/128, 256>>>((const float*)d_in[iEOW], (const float*)d_in[iEOB],
                                     (const float*)d_in[iATT], esrc);
    dst_kernel<<<N_DST/8, 256>>>((const float*)d_in[iNW], (const float*)d_in[iNB], out);
}

// round 16
// speedup vs baseline: 1.0719x; 1.0400x over previous
#include <cuda_runtime.h>
#include <cuda_fp16.h>
#include <math.h>
#include <stdint.h>

#define N_SRC 16384
#define N_DST 8192
#define KNB 32
#define E_TOT (N_DST*KNB)
#define T 16
#define H 64
#define TILE 64

// ---- scratch ----
__device__ __half g_eout[(size_t)E_TOT*H];
__device__ __half g_aout[(size_t)E_TOT*H];
__device__ __half g_m[(size_t)E_TOT*H];
__device__ float g_a[E_TOT];
__device__ float g_P[N_SRC*H];
__device__ float g_Q[N_DST*H];
__device__ int   g_list[E_TOT];
__device__ int   g_part[128][16];
__device__ int   g_cur[T];
__device__ __half g_B[2][256][88];
__device__ float  g_bias[2][256];
__device__ float  g_tv[16];

// ---- LSTM smem byte map (per CTA) ----
#define OFF_B    0
#define OFF_A    0
#define ABUF     11264
#define OFF_SIDX 45056
#define OFF_SLEN 45312
#define OFF_TV   45568
#define OFF_SMAX 45632
#define LSTM_SMEM 45696

__device__ __forceinline__ uint32_t smem_u32(const void* p){
    uint32_t a; asm("{ .reg .u64 t; cvta.to.shared.u64 t, %1; cvt.u32.u64 %0, t; }":"=r"(a):"l"(p)); return a;
}
__device__ __forceinline__ uint32_t amat(uint32_t base, int row, int ch){
    return base + (uint32_t)row*176u + ((uint32_t)ch << 4);
}
__device__ __forceinline__ uint32_t ael(uint32_t base, int row, int k){
    return base + (uint32_t)row*176u + ((uint32_t)k << 1);
}
__device__ __forceinline__ void ldm4(uint32_t addr, uint32_t &r0, uint32_t &r1, uint32_t &r2, uint32_t &r3){
    asm volatile("ldmatrix.sync.aligned.m8n8.x4.shared.b16 {%0,%1,%2,%3}, [%4];"
        : "=r"(r0),"=r"(r1),"=r"(r2),"=r"(r3) : "r"(addr));
}
__device__ __forceinline__ void mma_fp16(float* c, uint32_t a0,uint32_t a1,uint32_t a2,uint32_t a3,
                                         uint32_t b0, uint32_t b1){
    asm volatile("mma.sync.aligned.m16n8k16.row.col.f32.f16.f16.f32 "
        "{%0,%1,%2,%3}, {%4,%5,%6,%7}, {%8,%9}, {%0,%1,%2,%3};"
        : "+f"(c[0]),"+f"(c[1]),"+f"(c[2]),"+f"(c[3])
        : "r"(a0),"r"(a1),"r"(a2),"r"(a3),"r"(b0),"r"(b1));
}
__device__ __forceinline__ __half2 tanh2(__half2 x){
    uint32_t xi = *(uint32_t*)&x, yi;
    asm("tanh.approx.f16x2 %0, %1;" : "=r"(yi) : "r"(xi));
    return *(__half2*)&yi;
}
__device__ __forceinline__ uint32_t pack_h2(float a, float b){
    __half2 v; v.x = __float2half_rn(a); v.y = __float2half_rn(b);
    return *(uint32_t*)&v;
}

// ---- LSTM cell update (shared by peeled t=0 and main loop) ----
__device__ __forceinline__ void cell_up(const float* acc, __half2& c2ref,
    int lane, char* smem, uint32_t aW, int edge, int u0, bool last, __half* gp)
{
    const unsigned FULL = 0xffffffffu;
    const __half2 hhalf = __float2half2_rn(0.5f);
    float gi[2], gf[2], gg[2], go[2];
    #pragma unroll
    for (int f = 0; f < 2; f++){
        float d0 = acc[4*f], d1 = acc[4*f+1], d2 = acc[4*f+2], d3 = acc[4*f+3];
        float sx = (lane & 1) ? d0 : d2;
        float sy = (lane & 1) ? d1 : d3;
        float rx = __shfl_xor_sync(FULL, sx, 1);
        float ry = __shfl_xor_sync(FULL, sy, 1);
        if (lane & 1){ gi[f] = rx; gf[f] = ry; gg[f] = d2; go[f] = d3; }
        else         { gi[f] = d0; gf[f] = d1; gg[f] = rx; go[f] = ry; }
    }
    __half2 I2 = __floats2half2_rn(gi[0], gi[1]);
    __half2 F2 = __floats2half2_rn(gf[0], gf[1]);
    __half2 G2 = __floats2half2_rn(gg[0], gg[1]);
    __half2 O2 = __floats2half2_rn(go[0], go[1]);
    __half2 iv = __hfma2(tanh2(__hmul2(I2, hhalf)), hhalf, hhalf);
    __half2 fv = __hfma2(tanh2(__hmul2(F2, hhalf)), hhalf, hhalf);
    __half2 ov = __hfma2(tanh2(__hmul2(O2, hhalf)), hhalf, hhalf);
    __half2 gv = tanh2(G2);
    c2ref = __hfma2(fv, c2ref, __hmul2(iv, gv));
    __half2 h2 = __hmul2(ov, tanh2(c2ref));
    uint32_t h2u = *(uint32_t*)&h2;
    uint32_t hp = __shfl_xor_sync(FULL, h2u, 2);
    if (!(lane & 2)){
        uint32_t lo = __byte_perm(h2u, hp, 0x5410);
        uint32_t hi = __byte_perm(h2u, hp, 0x7632);
        *(uint32_t*)(smem + ael(aW, edge, u0))     = lo;
        *(uint32_t*)(smem + ael(aW, edge, u0 + 2)) = hi;
        if (last){
            *(uint32_t*)(gp + u0)     = lo;
            *(uint32_t*)(gp + u0 + 2) = hi;
        }
    }
}

// ---- bucketing ----
__global__ void hist_part_kernel(const int* __restrict__ elen){
    __shared__ int h[T];
    if (threadIdx.x < T) h[threadIdx.x] = 0;
    __syncthreads();
    int base = blockIdx.x * 2048;
    for (int i = threadIdx.x; i < 2048; i += 256) atomicAdd(&h[elen[base + i] - 1], 1);
    __syncthreads();
    if (threadIdx.x < T) g_part[blockIdx.x][threadIdx.x] = h[threadIdx.x];
}
__global__ void scan2_kernel(){
    __shared__ int cnt[T];
    if (threadIdx.x < T){
        int s = 0;
        for (int b = 0; b < 128; b++) s += g_part[b][threadIdx.x];
        cnt[threadIdx.x] = s;
    }
    __syncthreads();
    if (threadIdx.x == 0){
        int off = 0;
        for (int l = T-1; l >= 0; --l){ g_cur[l] = off; off += cnt[l]; }
    }
}
__global__ void scatter_kernel(const int* __restrict__ elen){
    int i = blockIdx.x*blockDim.x + threadIdx.x;
    if (i >= E_TOT) return;
    int l = elen[i]-1;
    unsigned act = __activemask();
    unsigned mask = __match_any_sync(act, l);
    int lane = threadIdx.x & 31, leader = __ffs(mask)-1;
    int rank = __popc(mask & ((1u<<lane)-1));
    int base = 0;
    if (lane == leader) base = atomicAdd(&g_cur[l], __popc(mask));
    base = __shfl_sync(mask, base, leader);
    g_list[base+rank] = i;
}

// ---- one-shot weight prep ----
__global__ void prep_b_kernel(
    const float* __restrict__ Wih_e, const float* __restrict__ Whh_e,
    const float* __restrict__ bih_e, const float* __restrict__ bhh_e,
    const float* __restrict__ Wih_a, const float* __restrict__ Whh_a,
    const float* __restrict__ bih_a, const float* __restrict__ bhh_a,
    const float* __restrict__ t2v_w, const float* __restrict__ t2v_b,
    const float* __restrict__ t2v_w0, const float* __restrict__ t2v_b0)
{
    const int isA = blockIdx.x;
    const float* Wih = isA ? Wih_a : Wih_e;
    const float* Whh = isA ? Whh_a : Whh_e;
    const float* bih = isA ? bih_a : bih_e;
    const float* bhh = isA ? bhh_a : bhh_e;
    int j = threadIdx.x;
    int srcj = (j & 3)*64 + (j >> 2);
    __half* row = g_B[isA][j];
    const float* whr = Whh + srcj*64;
    #pragma unroll 4
    for (int k = 0; k < 64; k++) row[k] = __float2half_rn(__ldg(whr + k));
    const float* wir = Wih + srcj*16;
    #pragma unroll
    for (int kk = 0; kk < 16; kk++) row[64 + kk] = __float2half_rn(__ldg(wir + kk));
    #pragma unroll
    for (int kk = 80; kk < 88; kk++) row[kk] = __float2half_rn(0.f);
    g_bias[isA][j] = __ldg(bih + srcj) + __ldg(bhh + srcj);
    if (isA == 0 && j < 16){
        float v;
        if (j < 7) v = t2v_w[j]; else if (j < 14) v = t2v_b[j-7];
        else if (j == 14) v = t2v_w0[0]; else v = t2v_b0[0];
        g_tv[j] = v;
    }
}

// ---- x fill (whole row per thread, tid < 64) ----
__device__ __forceinline__ void fill_x(char* smem, uint32_t ab, const float* sTv,
    const float* __restrict__ ef, const float* __restrict__ et, int eg, int t, int e)
{
    float x[16];
    const float4* p = (const float4*)(ef + ((size_t)eg*T + t)*8);
    float4 v0 = __ldg(p), v1 = __ldg(p+1);
    x[0]=v0.x;x[1]=v0.y;x[2]=v0.z;x[3]=v0.w;x[4]=v1.x;x[5]=v1.y;x[6]=v1.z;x[7]=v1.w;
    float tau = __ldg(et + (size_t)eg*T + t);
    #pragma unroll
    for (int k = 0; k < 7; k++) x[8+k] = __sinf(fmaf(tau, sTv[k], sTv[7+k]));
    x[15] = fmaf(tau, sTv[14], sTv[15]);
    #pragma unroll
    for (int u = 0; u < 16; u += 2)
        *(uint32_t*)(smem + ael(ab, e, 64 + u)) = pack_h2(x[u], x[u+1]);
}

// ---- LSTM: 256 threads, 8 warps (n32), 64 edges, 2 CTAs/SM, pipelined A,
//      t=0 peeled (x-only GEMM, no branches in steady-state loop) ----
__global__ void __launch_bounds__(256, 2) lstm_hmma_kernel(
    const float* __restrict__ ef, const float* __restrict__ et,
    const int*   __restrict__ elen)
{
    extern __shared__ char smem[];
    const uint32_t sb = smem_u32(smem);
    int*   sidx = (int*)(smem + OFF_SIDX);
    int*   slen = (int*)(smem + OFF_SLEN);
    float* sTv  = (float*)(smem + OFF_TV);
    int*   smax = (int*)(smem + OFF_SMAX);

    const int tid = threadIdx.x, wid = tid >> 5, lane = tid & 31;
    const int isA = blockIdx.y;
    __half* gout = isA ? g_aout : g_eout;

    if (tid == 0) *smax = 0;
    if (tid < 16) sTv[tid] = g_tv[tid];
    if (tid < TILE){
        int eg = g_list[blockIdx.x*TILE + tid];
        sidx[tid] = eg;
        int l = elen[eg];
        slen[tid] = l;
        atomicMax(smax, l);
    }
    {
        const float4* src = (const float4*)g_B[isA];
        float4* dst = (float4*)smem;
        #pragma unroll
        for (int i = 0; i < 11; i++) dst[tid + 256*i] = src[tid + 256*i];
    }
    __syncthreads();

    const int nw = wid;
    uint32_t Br[2][5][4];
    #pragma unroll
    for (int s = 0; s < 2; s++){
        int rowb = nw*32 + s*16 + ((lane >> 4) << 3) + (lane & 7);
        #pragma unroll
        for (int ks = 0; ks < 5; ks++){
            int chb = 2*ks + ((lane >> 3) & 1);
            ldm4(amat(sb + OFF_B, rowb, chb), Br[s][ks][0],Br[s][ks][1],Br[s][ks][2],Br[s][ks][3]);
        }
    }
    float bia[8];
    #pragma unroll
    for (int s = 0; s < 2; s++){
        int n0 = nw*32 + s*16 + 2*(lane & 3);
        bia[s*4+0] = __ldg(&g_bias[isA][n0]);
        bia[s*4+1] = __ldg(&g_bias[isA][n0+1]);
        bia[s*4+2] = __ldg(&g_bias[isA][n0+8]);
        bia[s*4+3] = __ldg(&g_bias[isA][n0+9]);
    }
    const int rc = (lane >> 2) + ((lane & 1) ? 8 : 0);
    int myg[4];
    uint32_t lens_pk = 0;
    #pragma unroll
    for (int i = 0; i < 4; i++){
        myg[i] = sidx[i*16 + rc];
        lens_pk |= (uint32_t)((slen[i*16 + rc] - 1) & 15) << (4*i);
    }
    __syncthreads();   // B smem reads done; A region may overwrite

    const int pedge = (tid < TILE) ? sidx[tid] : 0;
    if (tid < TILE) fill_x(smem, OFF_A, sTv, ef, et, pedge, 0, tid);
    __syncthreads();

    const int maxlen = *smax;
    const int ubase = nw*8;

    __half2 c2[8];
    #pragma unroll
    for (int i = 0; i < 8; i++) c2[i] = __float2half2_rn(0.f);

    // ---- peeled t = 0: only the x k-step (ks = 4); h == 0 ----
    {
        const uint32_t aR = OFF_A;
        const uint32_t aW = OFF_A + ABUF;
        if (tid < TILE && maxlen > 1)
            fill_x(smem, aW, sTv, ef, et, pedge, 1, tid);

        uint32_t Axb[2][4];
        {
            const int cc = 8 + (lane >> 4);
            ldm4(amat(sb + aR, (lane & 15), cc), Axb[0][0],Axb[0][1],Axb[0][2],Axb[0][3]);
        }
        #pragma unroll
        for (int i = 0; i < 4; i++){
            const int cur = i & 1, nxt = cur ^ 1;
            if (i < 3){
                const int cc = 8 + (lane >> 4);
                ldm4(amat(sb + aR, (i+1)*16 + (lane & 15), cc), Axb[nxt][0],Axb[nxt][1],Axb[nxt][2],Axb[nxt][3]);
            }
            const bool last = (0 == (int)((lens_pk >> (4*i)) & 15));
            const int edge = i*16 + rc;
            __half* gp = gout + (size_t)myg[i]*H;
            #pragma unroll
            for (int s = 0; s < 2; s++){
                float acc[8] = {bia[s*4+0], bia[s*4+1], bia[s*4+0], bia[s*4+1],
                                bia[s*4+2], bia[s*4+3], bia[s*4+2], bia[s*4+3]};
                mma_fp16(acc,   Axb[cur][0],Axb[cur][1],Axb[cur][2],Axb[cur][3], Br[s][4][0], Br[s][4][1]);
                mma_fp16(acc+4, Axb[cur][0],Axb[cur][1],Axb[cur][2],Axb[cur][3], Br[s][4][2], Br[s][4][3]);
                cell_up(acc, c2[i*2 + s], lane, smem, aW, edge, ubase + s*4, last, gp);
            }
        }
        __syncthreads();
    }

    // ---- steady state t = 1 .. maxlen-1: full K = 80, branch-free ----
    for (int t = 1; t < maxlen; ++t){
        const int par = t & 1;
        const uint32_t aR = OFF_A + par*ABUF;
        const uint32_t aW = OFF_A + (par^1)*ABUF;

        if (tid < TILE && (t+1) < maxlen)
            fill_x(smem, aW, sTv, ef, et, pedge, t+1, tid);

        uint32_t Afb[2][5][4];
        #pragma unroll
        for (int ks = 0; ks < 5; ks++){
            const int cc = 2*ks + (lane >> 4);
            ldm4(amat(sb + aR, (lane & 15), cc), Afb[0][ks][0],Afb[0][ks][1],Afb[0][ks][2],Afb[0][ks][3]);
        }
        #pragma unroll
        for (int i = 0; i < 4; i++){
            const int cur = i & 1, nxt = cur ^ 1;
            if (i < 3){
                const int r = (i+1)*16 + (lane & 15);
                #pragma unroll
                for (int ks = 0; ks < 5; ks++){
                    const int cc = 2*ks + (lane >> 4);
                    ldm4(amat(sb + aR, r, cc), Afb[nxt][ks][0],Afb[nxt][ks][1],Afb[nxt][ks][2],Afb[nxt][ks][3]);
                }
            }
            const bool last = (t == (int)((lens_pk >> (4*i)) & 15));
            const int edge = i*16 + rc;
            __half* gp = gout + (size_t)myg[i]*H;
            #pragma unroll
            for (int s = 0; s < 2; s++){
                float acc[8] = {bia[s*4+0], bia[s*4+1], bia[s*4+0], bia[s*4+1],
                                bia[s*4+2], bia[s*4+3], bia[s*4+2], bia[s*4+3]};
                #pragma unroll
                for (int ks = 0; ks < 5; ks++){
                    mma_fp16(acc,   Afb[cur][ks][0],Afb[cur][ks][1],Afb[cur][ks][2],Afb[cur][ks][3], Br[s][ks][0], Br[s][ks][1]);
                    mma_fp16(acc+4, Afb[cur][ks][0],Afb[cur][ks][1],Afb[cur][ks][2],Afb[cur][ks][3], Br[s][ks][2], Br[s][ks][3]);
                }
                cell_up(acc, c2[i*2 + s], lane, smem, aW, edge, ubase + s*4, last, gp);
            }
        }
        __syncthreads();
    }
}

// ---- projections: P = nf@eW1^T, Q = nf[:8192]@nW1^T ----
__global__ void proj_kernel(const float* __restrict__ nf,
                            const float* __restrict__ eW, const float* __restrict__ nW)
{
    __shared__ float Wt[64*64];
    __shared__ float xs[16*64];
    const float* W = blockIdx.y ? nW : eW;
    float* out = blockIdx.y ? g_Q : g_P;
    int nrows = blockIdx.y ? N_DST : N_SRC;
    int r0 = blockIdx.x*16;
    if (r0 >= nrows) return;
    int tid = threadIdx.x;
    for (int idx = tid; idx < 4096; idx += 256){ int d = idx>>6, j = idx&63; Wt[idx] = W[j*128 + d]; }
    for (int idx = tid; idx < 1024; idx += 256) xs[idx] = nf[(size_t)r0*64 + idx];
    __syncthreads();
    for (int o = tid; o < 1024; o += 256){
        int ri = o>>6, j = o&63;
        float s = 0.f;
        #pragma unroll
        for (int d = 0; d < 64; d++) s = fmaf(xs[ri*64+d], Wt[d*64+j], s);
        out[(size_t)(r0+ri)*64 + j] = s;
    }
}

// ---- edge epilogue via HMMA: 128 edges/block, warp = m16 x n64 x k64 ----
__global__ void __launch_bounds__(256) edgem_kernel(
    const float* __restrict__ eW, const float* __restrict__ eb,
    const float* __restrict__ attn, const int* __restrict__ esrc)
{
    __shared__ __half eo[128*72];
    __shared__ __half w2[64*72];
    __shared__ float att[64], bsh[64];
    const uint32_t eob = smem_u32(eo), w2b = smem_u32(w2);
    int tid = threadIdx.x, wid = tid >> 5, lane = tid & 31;
    size_t e0 = (size_t)blockIdx.x*128;

    for (int idx = tid; idx < 4096; idx += 256){
        int row = idx >> 5, cp = idx & 31;
        *(uint32_t*)&eo[row*72 + cp*2] = *(const uint32_t*)&g_eout[(e0 + row)*64 + cp*2];
    }
    for (int idx = tid; idx < 2048; idx += 256){
        int j = idx >> 5, cp = idx & 31;
        *(uint32_t*)&w2[j*72 + cp*2] = pack_h2(eW[j*128 + 64 + cp*2], eW[j*128 + 64 + cp*2 + 1]);
    }
    if (tid < 64){ att[tid] = attn[tid]; bsh[tid] = eb[tid]; }
    __syncthreads();

    uint32_t Af[4][4];
    #pragma unroll
    for (int ks = 0; ks < 4; ks++){
        uint32_t addr = eob + (uint32_t)(wid*16 + (lane & 15))*144u + (uint32_t)(2*ks + (lane >> 4))*16u;
        ldm4(addr, Af[ks][0],Af[ks][1],Af[ks][2],Af[ks][3]);
    }
    const int r0e = wid*16 + (lane >> 2);
    const int s0 = esrc[e0 + r0e];
    const int s1 = esrc[e0 + r0e + 8];

    #pragma unroll
    for (int ng = 0; ng < 4; ng++){
        float acc[8] = {0.f,0.f,0.f,0.f,0.f,0.f,0.f,0.f};
        #pragma unroll
        for (int ks = 0; ks < 4; ks++){
            int rowb = ng*16 + ((lane >> 4) << 3) + (lane & 7);
            int chb  = 2*ks + ((lane >> 3) & 1);
            uint32_t b0,b1,b2,b3;
            ldm4(w2b + (uint32_t)rowb*144u + (uint32_t)chb*16u, b0,b1,b2,b3);
            mma_fp16(acc,   Af[ks][0],Af[ks][1],Af[ks][2],Af[ks][3], b0, b1);
            mma_fp16(acc+4, Af[ks][0],Af[ks][1],Af[ks][2],Af[ks][3], b2, b3);
        }
        const int c0 = ng*16 + 2*(lane & 3);
        float2 p00 = *(const float2*)(g_P + (size_t)s0*64 + c0);
        float2 p01 = *(const float2*)(g_P + (size_t)s0*64 + c0 + 8);
        float2 p10 = *(const float2*)(g_P + (size_t)s1*64 + c0);
        float2 p11 = *(const float2*)(g_P + (size_t)s1*64 + c0 + 8);
        float b0v = bsh[c0], b1v = bsh[c0+1], b2v = bsh[c0+8], b3v = bsh[c0+9];
        *(uint32_t*)&g_m[(e0 + r0e)*64 + c0] =
            pack_h2(fmaxf(acc[0]+p00.x+b0v, 0.f), fmaxf(acc[1]+p00.y+b1v, 0.f));
        *(uint32_t*)&g_m[(e0 + r0e + 8)*64 + c0] =
            pack_h2(fmaxf(acc[2]+p10.x+b0v, 0.f), fmaxf(acc[3]+p10.y+b1v, 0.f));
        *(uint32_t*)&g_m[(e0 + r0e)*64 + c0 + 8] =
            pack_h2(fmaxf(acc[4]+p01.x+b2v, 0.f), fmaxf(acc[5]+p01.y+b3v, 0.f));
        *(uint32_t*)&g_m[(e0 + r0e + 8)*64 + c0 + 8] =
            pack_h2(fmaxf(acc[6]+p11.x+b2v, 0.f), fmaxf(acc[7]+p11.y+b3v, 0.f));
    }

    if (tid < 128){
        size_t e = e0 + tid;
        const __half2* ar = (const __half2*)&g_aout[e*64];
        float s = 0.f;
        #pragma unroll
        for (int d = 0; d < 32; d++){
            float2 v = __half22float2(ar[d]);
            s += v.x*att[2*d] + v.y*att[2*d+1];
        }
        g_a[e] = (s > 0.f) ? s : 0.01f*s;
    }
}

// ---- per-dst: sparsemax + aggregate + final MLP ----
__global__ void __launch_bounds__(256) dst_kernel(
    const float* __restrict__ nW, const float* __restrict__ nb, float* __restrict__ out)
{
    __shared__ float nW2t[64*64];
    __shared__ float nbs[64];
    __shared__ float hns[8][64];
    int tid = threadIdx.x;
    for (int idx = tid; idx < 4096; idx += 256){ int d = idx>>6, j = idx&63; nW2t[idx] = nW[j*128 + 64 + d]; }
    if (tid < 64) nbs[tid] = nb[tid];
    __syncthreads();
    int w = tid>>5, lane = tid&31;
    int dst = blockIdx.x*8 + w;
    const unsigned FULL = 0xffffffffu;

    float av = g_a[(size_t)dst*KNB + lane];
    float mx = av;
    #pragma unroll
    for (int o = 16; o > 0; o >>= 1) mx = fmaxf(mx, __shfl_xor_sync(FULL, mx, o));
    float z = av - mx;
    float v = z;
    #pragma unroll
    for (int k = 2; k <= 32; k <<= 1){
        #pragma unroll
        for (int j = k>>1; j > 0; j >>= 1){
            float o = __shfl_xor_sync(FULL, v, j);
            bool lower = (lane & j) == 0, asc = (lane & k) != 0;
            v = (lower == asc) ? fminf(v, o) : fmaxf(v, o);
        }
    }
    float cs = v;
    #pragma unroll
    for (int o = 1; o < 32; o <<= 1){
        float t = __shfl_up_sync(FULL, cs, o);
        if (lane >= o) cs += t;
    }
    float r = (float)(lane+1);
    bool gt = (1.f + r*v) > cs;
    float kk = gt ? r : 0.f, sz = gt ? v : 0.f;
    #pragma unroll
    for (int o = 16; o > 0; o >>= 1){
        kk = fmaxf(kk, __shfl_xor_sync(FULL, kk, o));
        sz += __shfl_xor_sync(FULL, sz, o);
    }
    float alpha = fmaxf(z - (sz - 1.f)/kk, 0.f);

    float hn0 = 0.f, hn1 = 0.f;
    #pragma unroll
    for (int k2 = 0; k2 < 32; k2++){
        float al = __shfl_sync(FULL, alpha, k2);
        if (al > 0.f){
            __half2 mv2 = *(const __half2*)&g_m[((size_t)dst*KNB + k2)*64 + lane*2];
            float2 mv = __half22float2(mv2);
            hn0 = fmaf(al, mv.x, hn0);
            hn1 = fmaf(al, mv.y, hn1);
        }
    }
    hns[w][lane*2] = hn0; hns[w][lane*2+1] = hn1;
    __syncwarp();
    float o0 = nbs[lane*2]   + g_Q[(size_t)dst*64 + lane*2];
    float o1 = nbs[lane*2+1] + g_Q[(size_t)dst*64 + lane*2+1];
    #pragma unroll 8
    for (int d = 0; d < 64; d++){
        float h = hns[w][d];
        float2 wv = *(const float2*)(nW2t + d*64 + lane*2);
        o0 = fmaf(h, wv.x, o0);
        o1 = fmaf(h, wv.y, o1);
    }
    size_t ob = (size_t)dst*64 + lane*2;
    out[ob] = fmaxf(o0, 0.f);
    out[ob+1] = fmaxf(o1, 0.f);
}

// ---- launcher ----
extern "C" void kernel_launch(void* const* d_in, const int* in_sizes, int n_in,
                              void* d_out, int out_size)
{
    int iNF,iEF,iET,iLEN,iSRC,iT2W,iT2B,iT2W0,iT2B0;
    int iEWih,iEWhh,iEBih,iEBhh,iAWih,iAWhh,iABih,iABhh,iATT,iEOW,iEOB,iNW,iNB;
    if (in_sizes[3] == E_TOT){
        iNF=0;iEF=1;iET=2;iLEN=3;iSRC=4;iT2W=5;iT2B=6;iT2W0=7;iT2B0=8;
        iEWih=9;iEWhh=10;iEBih=11;iEBhh=12;iAWih=13;iAWhh=14;iABih=15;iABhh=16;
        iATT=17;iEOW=18;iEOB=19;iNW=20;iNB=21;
    } else {
        iNF=0;iEF=1;iET=2;iT2W=3;iT2B=4;iT2W0=5;iT2B0=6;
        iEWih=7;iEWhh=8;iEBih=9;iEBhh=10;iAWih=11;iAWhh=12;iABih=13;iABhh=14;
        iATT=15;iEOW=16;iEOB=17;iNW=18;iNB=19;iLEN=20;iSRC=21;
    }
    const float* nf   = (const float*)d_in[iNF];
    const float* ef   = (const float*)d_in[iEF];
    const float* et   = (const float*)d_in[iET];
    const int*   elen = (const int*)  d_in[iLEN];
    const int*   esrc = (const int*)  d_in[iSRC];
    float* out = (float*)d_out;

    cudaFuncSetAttribute(lstm_hmma_kernel, cudaFuncAttributeMaxDynamicSharedMemorySize, LSTM_SMEM);

    hist_part_kernel<<<128, 256>>>(elen);
    prep_b_kernel<<<2, 256>>>(
        (const float*)d_in[iEWih], (const float*)d_in[iEWhh],
        (const float*)d_in[iEBih], (const float*)d_in[iEBhh],
        (const float*)d_in[iAWih], (const float*)d_in[iAWhh],
        (const float*)d_in[iABih], (const float*)d_in[iABhh],
        (const float*)d_in[iT2W], (const float*)d_in[iT2B],
        (const float*)d_in[iT2W0], (const float*)d_in[iT2B0]);
    scan2_kernel<<<1, 256>>>();
    scatter_kernel<<<E_TOT/256, 256>>>(elen);

    lstm_hmma_kernel<<<dim3(E_TOT/TILE, 2), 256, LSTM_SMEM>>>(ef, et, elen);

    proj_kernel<<<dim3(N_SRC/16, 2), 256>>>(nf, (const float*)d_in[iEOW], (const float*)d_in[iNW]);
    edgem_kernel<<<E_TOT/128, 256>>>((const float*)d_in[iEOW], (const float*)d_in[iEOB],
                                     (const float*)d_in[iATT], esrc);
    dst_kernel<<<N_DST/8, 256>>>((const float*)d_in[iNW], (const float*)d_in[iNB], out);
}

// round 17
// speedup vs baseline: 1.0956x; 1.0221x over previous
#include <cuda_runtime.h>
#include <cuda_fp16.h>
#include <math.h>
#include <stdint.h>

#define N_SRC 16384
#define N_DST 8192
#define KNB 32
#define E_TOT (N_DST*KNB)
#define T 16
#define H 64
#define TILE 64

// ---- scratch ----
__device__ __half g_eout[(size_t)E_TOT*H];
__device__ __half g_aout[(size_t)E_TOT*H];
__device__ __half g_m[(size_t)E_TOT*H];
__device__ float g_a[E_TOT];
__device__ float g_P[N_SRC*H];
__device__ float g_Q[N_DST*H];
__device__ int   g_list[E_TOT];
__device__ int   g_part[128][16];
__device__ int   g_cur[T];
__device__ __half g_B[2][256][88];
__device__ float  g_bias[2][256];
__device__ float  g_tv[16];

// ---- LSTM smem byte map (per CTA) ----
#define OFF_B    0
#define OFF_A    0
#define ABUF     11264
#define OFF_SIDX 45056
#define OFF_SLEN 45312
#define OFF_TV   45568
#define OFF_SMAX 45632
#define LSTM_SMEM 45696

__device__ __forceinline__ uint32_t smem_u32(const void* p){
    uint32_t a; asm("{ .reg .u64 t; cvta.to.shared.u64 t, %1; cvt.u32.u64 %0, t; }":"=r"(a):"l"(p)); return a;
}
__device__ __forceinline__ uint32_t amat(uint32_t base, int row, int ch){
    return base + (uint32_t)row*176u + ((uint32_t)ch << 4);
}
__device__ __forceinline__ uint32_t ael(uint32_t base, int row, int k){
    return base + (uint32_t)row*176u + ((uint32_t)k << 1);
}
__device__ __forceinline__ void ldm4(uint32_t addr, uint32_t &r0, uint32_t &r1, uint32_t &r2, uint32_t &r3){
    asm volatile("ldmatrix.sync.aligned.m8n8.x4.shared.b16 {%0,%1,%2,%3}, [%4];"
        : "=r"(r0),"=r"(r1),"=r"(r2),"=r"(r3) : "r"(addr));
}
__device__ __forceinline__ void mma_fp16(float* c, uint32_t a0,uint32_t a1,uint32_t a2,uint32_t a3,
                                         uint32_t b0, uint32_t b1){
    asm volatile("mma.sync.aligned.m16n8k16.row.col.f32.f16.f16.f32 "
        "{%0,%1,%2,%3}, {%4,%5,%6,%7}, {%8,%9}, {%0,%1,%2,%3};"
        : "+f"(c[0]),"+f"(c[1]),"+f"(c[2]),"+f"(c[3])
        : "r"(a0),"r"(a1),"r"(a2),"r"(a3),"r"(b0),"r"(b1));
}
__device__ __forceinline__ __half2 tanh2(__half2 x){
    uint32_t xi = *(uint32_t*)&x, yi;
    asm("tanh.approx.f16x2 %0, %1;" : "=r"(yi) : "r"(xi));
    return *(__half2*)&yi;
}
__device__ __forceinline__ uint32_t pack_h2(float a, float b){
    __half2 v; v.x = __float2half_rn(a); v.y = __float2half_rn(b);
    return *(uint32_t*)&v;
}

// ---- LSTM cell update ----
__device__ __forceinline__ void cell_up(const float* acc, __half2& c2ref,
    int lane, char* smem, uint32_t aW, int edge, int u0, bool last, __half* gp)
{
    const unsigned FULL = 0xffffffffu;
    const __half2 hhalf = __float2half2_rn(0.5f);
    float gi[2], gf[2], gg[2], go[2];
    #pragma unroll
    for (int f = 0; f < 2; f++){
        float d0 = acc[4*f], d1 = acc[4*f+1], d2 = acc[4*f+2], d3 = acc[4*f+3];
        float sx = (lane & 1) ? d0 : d2;
        float sy = (lane & 1) ? d1 : d3;
        float rx = __shfl_xor_sync(FULL, sx, 1);
        float ry = __shfl_xor_sync(FULL, sy, 1);
        if (lane & 1){ gi[f] = rx; gf[f] = ry; gg[f] = d2; go[f] = d3; }
        else         { gi[f] = d0; gf[f] = d1; gg[f] = rx; go[f] = ry; }
    }
    __half2 I2 = __floats2half2_rn(gi[0], gi[1]);
    __half2 F2 = __floats2half2_rn(gf[0], gf[1]);
    __half2 G2 = __floats2half2_rn(gg[0], gg[1]);
    __half2 O2 = __floats2half2_rn(go[0], go[1]);
    __half2 iv = __hfma2(tanh2(__hmul2(I2, hhalf)), hhalf, hhalf);
    __half2 fv = __hfma2(tanh2(__hmul2(F2, hhalf)), hhalf, hhalf);
    __half2 ov = __hfma2(tanh2(__hmul2(O2, hhalf)), hhalf, hhalf);
    __half2 gv = tanh2(G2);
    c2ref = __hfma2(fv, c2ref, __hmul2(iv, gv));
    __half2 h2 = __hmul2(ov, tanh2(c2ref));
    uint32_t h2u = *(uint32_t*)&h2;
    uint32_t hp = __shfl_xor_sync(FULL, h2u, 2);
    if (!(lane & 2)){
        uint32_t lo = __byte_perm(h2u, hp, 0x5410);
        uint32_t hi = __byte_perm(h2u, hp, 0x7632);
        *(uint32_t*)(smem + ael(aW, edge, u0))     = lo;
        *(uint32_t*)(smem + ael(aW, edge, u0 + 2)) = hi;
        if (last){
            *(uint32_t*)(gp + u0)     = lo;
            *(uint32_t*)(gp + u0 + 2) = hi;
        }
    }
}

// ---- bucketing ----
__global__ void hist_part_kernel(const int* __restrict__ elen){
    __shared__ int h[T];
    if (threadIdx.x < T) h[threadIdx.x] = 0;
    __syncthreads();
    int base = blockIdx.x * 2048;
    for (int i = threadIdx.x; i < 2048; i += 256) atomicAdd(&h[elen[base + i] - 1], 1);
    __syncthreads();
    if (threadIdx.x < T) g_part[blockIdx.x][threadIdx.x] = h[threadIdx.x];
}
__global__ void scan2_kernel(){
    __shared__ int cnt[T];
    if (threadIdx.x < T){
        int s = 0;
        for (int b = 0; b < 128; b++) s += g_part[b][threadIdx.x];
        cnt[threadIdx.x] = s;
    }
    __syncthreads();
    if (threadIdx.x == 0){
        int off = 0;
        for (int l = T-1; l >= 0; --l){ g_cur[l] = off; off += cnt[l]; }
    }
}
__global__ void scatter_kernel(const int* __restrict__ elen){
    int i = blockIdx.x*blockDim.x + threadIdx.x;
    if (i >= E_TOT) return;
    int l = elen[i]-1;
    unsigned act = __activemask();
    unsigned mask = __match_any_sync(act, l);
    int lane = threadIdx.x & 31, leader = __ffs(mask)-1;
    int rank = __popc(mask & ((1u<<lane)-1));
    int base = 0;
    if (lane == leader) base = atomicAdd(&g_cur[l], __popc(mask));
    base = __shfl_sync(mask, base, leader);
    g_list[base+rank] = i;
}

// ---- one-shot weight prep ----
__global__ void prep_b_kernel(
    const float* __restrict__ Wih_e, const float* __restrict__ Whh_e,
    const float* __restrict__ bih_e, const float* __restrict__ bhh_e,
    const float* __restrict__ Wih_a, const float* __restrict__ Whh_a,
    const float* __restrict__ bih_a, const float* __restrict__ bhh_a,
    const float* __restrict__ t2v_w, const float* __restrict__ t2v_b,
    const float* __restrict__ t2v_w0, const float* __restrict__ t2v_b0)
{
    const int isA = blockIdx.x;
    const float* Wih = isA ? Wih_a : Wih_e;
    const float* Whh = isA ? Whh_a : Whh_e;
    const float* bih = isA ? bih_a : bih_e;
    const float* bhh = isA ? bhh_a : bhh_e;
    int j = threadIdx.x;
    int srcj = (j & 3)*64 + (j >> 2);
    __half* row = g_B[isA][j];
    const float* whr = Whh + srcj*64;
    #pragma unroll 4
    for (int k = 0; k < 64; k++) row[k] = __float2half_rn(__ldg(whr + k));
    const float* wir = Wih + srcj*16;
    #pragma unroll
    for (int kk = 0; kk < 16; kk++) row[64 + kk] = __float2half_rn(__ldg(wir + kk));
    #pragma unroll
    for (int kk = 80; kk < 88; kk++) row[kk] = __float2half_rn(0.f);
    g_bias[isA][j] = __ldg(bih + srcj) + __ldg(bhh + srcj);
    if (isA == 0 && j < 16){
        float v;
        if (j < 7) v = t2v_w[j]; else if (j < 14) v = t2v_b[j-7];
        else if (j == 14) v = t2v_w0[0]; else v = t2v_b0[0];
        g_tv[j] = v;
    }
}

// ---- x fill ----
__device__ __forceinline__ void fill_x(char* smem, uint32_t ab, const float* sTv,
    const float* __restrict__ ef, const float* __restrict__ et, int eg, int t, int e)
{
    float x[16];
    const float4* p = (const float4*)(ef + ((size_t)eg*T + t)*8);
    float4 v0 = __ldg(p), v1 = __ldg(p+1);
    x[0]=v0.x;x[1]=v0.y;x[2]=v0.z;x[3]=v0.w;x[4]=v1.x;x[5]=v1.y;x[6]=v1.z;x[7]=v1.w;
    float tau = __ldg(et + (size_t)eg*T + t);
    #pragma unroll
    for (int k = 0; k < 7; k++) x[8+k] = __sinf(fmaf(tau, sTv[k], sTv[7+k]));
    x[15] = fmaf(tau, sTv[14], sTv[15]);
    #pragma unroll
    for (int u = 0; u < 16; u += 2)
        *(uint32_t*)(smem + ael(ab, e, 64 + u)) = pack_h2(x[u], x[u+1]);
}

// ---- LSTM: unchanged R16 winner ----
__global__ void __launch_bounds__(256, 2) lstm_hmma_kernel(
    const float* __restrict__ ef, const float* __restrict__ et,
    const int*   __restrict__ elen)
{
    extern __shared__ char smem[];
    const uint32_t sb = smem_u32(smem);
    int*   sidx = (int*)(smem + OFF_SIDX);
    int*   slen = (int*)(smem + OFF_SLEN);
    float* sTv  = (float*)(smem + OFF_TV);
    int*   smax = (int*)(smem + OFF_SMAX);

    const int tid = threadIdx.x, wid = tid >> 5, lane = tid & 31;
    const int isA = blockIdx.y;
    __half* gout = isA ? g_aout : g_eout;

    if (tid == 0) *smax = 0;
    if (tid < 16) sTv[tid] = g_tv[tid];
    if (tid < TILE){
        int eg = g_list[blockIdx.x*TILE + tid];
        sidx[tid] = eg;
        int l = elen[eg];
        slen[tid] = l;
        atomicMax(smax, l);
    }
    {
        const float4* src = (const float4*)g_B[isA];
        float4* dst = (float4*)smem;
        #pragma unroll
        for (int i = 0; i < 11; i++) dst[tid + 256*i] = src[tid + 256*i];
    }
    __syncthreads();

    const int nw = wid;
    uint32_t Br[2][5][4];
    #pragma unroll
    for (int s = 0; s < 2; s++){
        int rowb = nw*32 + s*16 + ((lane >> 4) << 3) + (lane & 7);
        #pragma unroll
        for (int ks = 0; ks < 5; ks++){
            int chb = 2*ks + ((lane >> 3) & 1);
            ldm4(amat(sb + OFF_B, rowb, chb), Br[s][ks][0],Br[s][ks][1],Br[s][ks][2],Br[s][ks][3]);
        }
    }
    float bia[8];
    #pragma unroll
    for (int s = 0; s < 2; s++){
        int n0 = nw*32 + s*16 + 2*(lane & 3);
        bia[s*4+0] = __ldg(&g_bias[isA][n0]);
        bia[s*4+1] = __ldg(&g_bias[isA][n0+1]);
        bia[s*4+2] = __ldg(&g_bias[isA][n0+8]);
        bia[s*4+3] = __ldg(&g_bias[isA][n0+9]);
    }
    const int rc = (lane >> 2) + ((lane & 1) ? 8 : 0);
    int myg[4];
    uint32_t lens_pk = 0;
    #pragma unroll
    for (int i = 0; i < 4; i++){
        myg[i] = sidx[i*16 + rc];
        lens_pk |= (uint32_t)((slen[i*16 + rc] - 1) & 15) << (4*i);
    }
    __syncthreads();

    const int pedge = (tid < TILE) ? sidx[tid] : 0;
    if (tid < TILE) fill_x(smem, OFF_A, sTv, ef, et, pedge, 0, tid);
    __syncthreads();

    const int maxlen = *smax;
    const int ubase = nw*8;

    __half2 c2[8];
    #pragma unroll
    for (int i = 0; i < 8; i++) c2[i] = __float2half2_rn(0.f);

    // ---- peeled t = 0 ----
    {
        const uint32_t aR = OFF_A;
        const uint32_t aW = OFF_A + ABUF;
        if (tid < TILE && maxlen > 1)
            fill_x(smem, aW, sTv, ef, et, pedge, 1, tid);

        uint32_t Axb[2][4];
        {
            const int cc = 8 + (lane >> 4);
            ldm4(amat(sb + aR, (lane & 15), cc), Axb[0][0],Axb[0][1],Axb[0][2],Axb[0][3]);
        }
        #pragma unroll
        for (int i = 0; i < 4; i++){
            const int cur = i & 1, nxt = cur ^ 1;
            if (i < 3){
                const int cc = 8 + (lane >> 4);
                ldm4(amat(sb + aR, (i+1)*16 + (lane & 15), cc), Axb[nxt][0],Axb[nxt][1],Axb[nxt][2],Axb[nxt][3]);
            }
            const bool last = (0 == (int)((lens_pk >> (4*i)) & 15));
            const int edge = i*16 + rc;
            __half* gp = gout + (size_t)myg[i]*H;
            #pragma unroll
            for (int s = 0; s < 2; s++){
                float acc[8] = {bia[s*4+0], bia[s*4+1], bia[s*4+0], bia[s*4+1],
                                bia[s*4+2], bia[s*4+3], bia[s*4+2], bia[s*4+3]};
                mma_fp16(acc,   Axb[cur][0],Axb[cur][1],Axb[cur][2],Axb[cur][3], Br[s][4][0], Br[s][4][1]);
                mma_fp16(acc+4, Axb[cur][0],Axb[cur][1],Axb[cur][2],Axb[cur][3], Br[s][4][2], Br[s][4][3]);
                cell_up(acc, c2[i*2 + s], lane, smem, aW, edge, ubase + s*4, last, gp);
            }
        }
        __syncthreads();
    }

    // ---- steady state ----
    for (int t = 1; t < maxlen; ++t){
        const int par = t & 1;
        const uint32_t aR = OFF_A + par*ABUF;
        const uint32_t aW = OFF_A + (par^1)*ABUF;

        if (tid < TILE && (t+1) < maxlen)
            fill_x(smem, aW, sTv, ef, et, pedge, t+1, tid);

        uint32_t Afb[2][5][4];
        #pragma unroll
        for (int ks = 0; ks < 5; ks++){
            const int cc = 2*ks + (lane >> 4);
            ldm4(amat(sb + aR, (lane & 15), cc), Afb[0][ks][0],Afb[0][ks][1],Afb[0][ks][2],Afb[0][ks][3]);
        }
        #pragma unroll
        for (int i = 0; i < 4; i++){
            const int cur = i & 1, nxt = cur ^ 1;
            if (i < 3){
                const int r = (i+1)*16 + (lane & 15);
                #pragma unroll
                for (int ks = 0; ks < 5; ks++){
                    const int cc = 2*ks + (lane >> 4);
                    ldm4(amat(sb + aR, r, cc), Afb[nxt][ks][0],Afb[nxt][ks][1],Afb[nxt][ks][2],Afb[nxt][ks][3]);
                }
            }
            const bool last = (t == (int)((lens_pk >> (4*i)) & 15));
            const int edge = i*16 + rc;
            __half* gp = gout + (size_t)myg[i]*H;
            #pragma unroll
            for (int s = 0; s < 2; s++){
                float acc[8] = {bia[s*4+0], bia[s*4+1], bia[s*4+0], bia[s*4+1],
                                bia[s*4+2], bia[s*4+3], bia[s*4+2], bia[s*4+3]};
                #pragma unroll
                for (int ks = 0; ks < 5; ks++){
                    mma_fp16(acc,   Afb[cur][ks][0],Afb[cur][ks][1],Afb[cur][ks][2],Afb[cur][ks][3], Br[s][ks][0], Br[s][ks][1]);
                    mma_fp16(acc+4, Afb[cur][ks][0],Afb[cur][ks][1],Afb[cur][ks][2],Afb[cur][ks][3], Br[s][ks][2], Br[s][ks][3]);
                }
                cell_up(acc, c2[i*2 + s], lane, smem, aW, edge, ubase + s*4, last, gp);
            }
        }
        __syncthreads();
    }
}

// ---- projections: 64 rows/block (4x W-staging amortization) ----
__global__ void __launch_bounds__(256) proj_kernel(
    const float* __restrict__ nf,
    const float* __restrict__ eW, const float* __restrict__ nW)
{
    __shared__ float Wt[64*64];
    __shared__ float xs[64*64];
    const float* W = blockIdx.y ? nW : eW;
    float* out = blockIdx.y ? g_Q : g_P;
    int nrows = blockIdx.y ? N_DST : N_SRC;
    int r0 = blockIdx.x*64;
    if (r0 >= nrows) return;
    int tid = threadIdx.x;
    for (int idx = tid; idx < 4096; idx += 256){ int d = idx>>6, j = idx&63; Wt[idx] = W[j*128 + d]; }
    for (int idx = tid; idx < 4096; idx += 256) xs[idx] = nf[(size_t)r0*64 + idx];
    __syncthreads();
    for (int o = tid; o < 4096; o += 256){
        int ri = o>>6, j = o&63;
        float s = 0.f;
        #pragma unroll
        for (int d = 0; d < 64; d++) s = fmaf(xs[ri*64+d], Wt[d*64+j], s);
        out[(size_t)(r0+ri)*64 + j] = s;
    }
}

// ---- edge epilogue via HMMA: 256 edges/block (2x w2 amortization) ----
__global__ void __launch_bounds__(256) edgem_kernel(
    const float* __restrict__ eW, const float* __restrict__ eb,
    const float* __restrict__ attn, const int* __restrict__ esrc)
{
    __shared__ __half eo[256*72];    // 36864 B
    __shared__ __half w2[64*72];     // 9216 B
    __shared__ float att[64], bsh[64];
    const uint32_t eob = smem_u32(eo), w2b = smem_u32(w2);
    int tid = threadIdx.x, wid = tid >> 5, lane = tid & 31;
    size_t e0 = (size_t)blockIdx.x*256;

    for (int idx = tid; idx < 8192; idx += 256){
        int row = idx >> 5, cp = idx & 31;
        *(uint32_t*)&eo[row*72 + cp*2] = *(const uint32_t*)&g_eout[(e0 + row)*64 + cp*2];
    }
    for (int idx = tid; idx < 2048; idx += 256){
        int j = idx >> 5, cp = idx & 31;
        *(uint32_t*)&w2[j*72 + cp*2] = pack_h2(eW[j*128 + 64 + cp*2], eW[j*128 + 64 + cp*2 + 1]);
    }
    if (tid < 64){ att[tid] = attn[tid]; bsh[tid] = eb[tid]; }
    __syncthreads();

    #pragma unroll
    for (int mt = 0; mt < 2; mt++){
        const int rbase = mt*128 + wid*16;
        uint32_t Af[4][4];
        #pragma unroll
        for (int ks = 0; ks < 4; ks++){
            uint32_t addr = eob + (uint32_t)(rbase + (lane & 15))*144u + (uint32_t)(2*ks + (lane >> 4))*16u;
            ldm4(addr, Af[ks][0],Af[ks][1],Af[ks][2],Af[ks][3]);
        }
        const int r0e = rbase + (lane >> 2);
        const int s0 = esrc[e0 + r0e];
        const int s1 = esrc[e0 + r0e + 8];

        #pragma unroll
        for (int ng = 0; ng < 4; ng++){
            float acc[8] = {0.f,0.f,0.f,0.f,0.f,0.f,0.f,0.f};
            #pragma unroll
            for (int ks = 0; ks < 4; ks++){
                int rowb = ng*16 + ((lane >> 4) << 3) + (lane & 7);
                int chb  = 2*ks + ((lane >> 3) & 1);
                uint32_t b0,b1,b2,b3;
                ldm4(w2b + (uint32_t)rowb*144u + (uint32_t)chb*16u, b0,b1,b2,b3);
                mma_fp16(acc,   Af[ks][0],Af[ks][1],Af[ks][2],Af[ks][3], b0, b1);
                mma_fp16(acc+4, Af[ks][0],Af[ks][1],Af[ks][2],Af[ks][3], b2, b3);
            }
            const int c0 = ng*16 + 2*(lane & 3);
            float2 p00 = *(const float2*)(g_P + (size_t)s0*64 + c0);
            float2 p01 = *(const float2*)(g_P + (size_t)s0*64 + c0 + 8);
            float2 p10 = *(const float2*)(g_P + (size_t)s1*64 + c0);
            float2 p11 = *(const float2*)(g_P + (size_t)s1*64 + c0 + 8);
            float b0v = bsh[c0], b1v = bsh[c0+1], b2v = bsh[c0+8], b3v = bsh[c0+9];
            *(uint32_t*)&g_m[(e0 + r0e)*64 + c0] =
                pack_h2(fmaxf(acc[0]+p00.x+b0v, 0.f), fmaxf(acc[1]+p00.y+b1v, 0.f));
            *(uint32_t*)&g_m[(e0 + r0e + 8)*64 + c0] =
                pack_h2(fmaxf(acc[2]+p10.x+b0v, 0.f), fmaxf(acc[3]+p10.y+b1v, 0.f));
            *(uint32_t*)&g_m[(e0 + r0e)*64 + c0 + 8] =
                pack_h2(fmaxf(acc[4]+p01.x+b2v, 0.f), fmaxf(acc[5]+p01.y+b3v, 0.f));
            *(uint32_t*)&g_m[(e0 + r0e + 8)*64 + c0 + 8] =
                pack_h2(fmaxf(acc[6]+p11.x+b2v, 0.f), fmaxf(acc[7]+p11.y+b3v, 0.f));
        }
    }

    {
        size_t e = e0 + tid;
        const __half2* ar = (const __half2*)&g_aout[e*64];
        float s = 0.f;
        #pragma unroll
        for (int d = 0; d < 32; d++){
            float2 v = __half22float2(ar[d]);
            s += v.x*att[2*d] + v.y*att[2*d+1];
        }
        g_a[e] = (s > 0.f) ? s : 0.01f*s;
    }
}

// ---- per-dst: sparsemax + aggregate + final MLP ----
__global__ void __launch_bounds__(256) dst_kernel(
    const float* __restrict__ nW, const float* __restrict__ nb, float* __restrict__ out)
{
    __shared__ float nW2t[64*64];
    __shared__ float nbs[64];
    __shared__ float hns[8][64];
    int tid = threadIdx.x;
    for (int idx = tid; idx < 4096; idx += 256){ int d = idx>>6, j = idx&63; nW2t[idx] = nW[j*128 + 64 + d]; }
    if (tid < 64) nbs[tid] = nb[tid];
    __syncthreads();
    int w = tid>>5, lane = tid&31;
    int dst = blockIdx.x*8 + w;
    const unsigned FULL = 0xffffffffu;

    float av = g_a[(size_t)dst*KNB + lane];
    float mx = av;
    #pragma unroll
    for (int o = 16; o > 0; o >>= 1) mx = fmaxf(mx, __shfl_xor_sync(FULL, mx, o));
    float z = av - mx;
    float v = z;
    #pragma unroll
    for (int k = 2; k <= 32; k <<= 1){
        #pragma unroll
        for (int j = k>>1; j > 0; j >>= 1){
            float o = __shfl_xor_sync(FULL, v, j);
            bool lower = (lane & j) == 0, asc = (lane & k) != 0;
            v = (lower == asc) ? fminf(v, o) : fmaxf(v, o);
        }
    }
    float cs = v;
    #pragma unroll
    for (int o = 1; o < 32; o <<= 1){
        float t = __shfl_up_sync(FULL, cs, o);
        if (lane >= o) cs += t;
    }
    float r = (float)(lane+1);
    bool gt = (1.f + r*v) > cs;
    float kk = gt ? r : 0.f, sz = gt ? v : 0.f;
    #pragma unroll
    for (int o = 16; o > 0; o >>= 1){
        kk = fmaxf(kk, __shfl_xor_sync(FULL, kk, o));
        sz += __shfl_xor_sync(FULL, sz, o);
    }
    float alpha = fmaxf(z - (sz - 1.f)/kk, 0.f);

    float hn0 = 0.f, hn1 = 0.f;
    #pragma unroll
    for (int k2 = 0; k2 < 32; k2++){
        float al = __shfl_sync(FULL, alpha, k2);
        if (al > 0.f){
            __half2 mv2 = *(const __half2*)&g_m[((size_t)dst*KNB + k2)*64 + lane*2];
            float2 mv = __half22float2(mv2);
            hn0 = fmaf(al, mv.x, hn0);
            hn1 = fmaf(al, mv.y, hn1);
        }
    }
    hns[w][lane*2] = hn0; hns[w][lane*2+1] = hn1;
    __syncwarp();
    float o0 = nbs[lane*2]   + g_Q[(size_t)dst*64 + lane*2];
    float o1 = nbs[lane*2+1] + g_Q[(size_t)dst*64 + lane*2+1];
    #pragma unroll 8
    for (int d = 0; d < 64; d++){
        float h = hns[w][d];
        float2 wv = *(const float2*)(nW2t + d*64 + lane*2);
        o0 = fmaf(h, wv.x, o0);
        o1 = fmaf(h, wv.y, o1);
    }
    size_t ob = (size_t)dst*64 + lane*2;
    out[ob] = fmaxf(o0, 0.f);
    out[ob+1] = fmaxf(o1, 0.f);
}

// ---- launcher ----
extern "C" void kernel_launch(void* const* d_in, const int* in_sizes, int n_in,
                              void* d_out, int out_size)
{
    int iNF,iEF,iET,iLEN,iSRC,iT2W,iT2B,iT2W0,iT2B0;
    int iEWih,iEWhh,iEBih,iEBhh,iAWih,iAWhh,iABih,iABhh,iATT,iEOW,iEOB,iNW,iNB;
    if (in_sizes[3] == E_TOT){
        iNF=0;iEF=1;iET=2;iLEN=3;iSRC=4;iT2W=5;iT2B=6;iT2W0=7;iT2B0=8;
        iEWih=9;iEWhh=10;iEBih=11;iEBhh=12;iAWih=13;iAWhh=14;iABih=15;iABhh=16;
        iATT=17;iEOW=18;iEOB=19;iNW=20;iNB=21;
    } else {
        iNF=0;iEF=1;iET=2;iT2W=3;iT2B=4;iT2W0=5;iT2B0=6;
        iEWih=7;iEWhh=8;iEBih=9;iEBhh=10;iAWih=11;iAWhh=12;iABih=13;iABhh=14;
        iATT=15;iEOW=16;iEOB=17;iNW=18;iNB=19;iLEN=20;iSRC=21;
    }
    const float* nf   = (const float*)d_in[iNF];
    const float* ef   = (const float*)d_in[iEF];
    const float* et   = (const float*)d_in[iET];
    const int*   elen = (const int*)  d_in[iLEN];
    const int*   esrc = (const int*)  d_in[iSRC];
    float* out = (float*)d_out;

    cudaFuncSetAttribute(lstm_hmma_kernel, cudaFuncAttributeMaxDynamicSharedMemorySize, LSTM_SMEM);

    hist_part_kernel<<<128, 256>>>(elen);
    prep_b_kernel<<<2, 256>>>(
        (const float*)d_in[iEWih], (const float*)d_in[iEWhh],
        (const float*)d_in[iEBih], (const float*)d_in[iEBhh],
        (const float*)d_in[iAWih], (const float*)d_in[iAWhh],
        (const float*)d_in[iABih], (const float*)d_in[iABhh],
        (const float*)d_in[iT2W], (const float*)d_in[iT2B],
        (const float*)d_in[iT2W0], (const float*)d_in[iT2B0]);
    scan2_kernel<<<1, 256>>>();
    scatter_kernel<<<E_TOT/256, 256>>>(elen);

    lstm_hmma_kernel<<<dim3(E_TOT/TILE, 2), 256, LSTM_SMEM>>>(ef, et, elen);

    proj_kernel<<<dim3(N_SRC/64, 2), 256>>>(nf, (const float*)d_in[iEOW], (const float*)d_in[iNW]);
    edgem_kernel<<<E_TOT/256, 256>>>((const float*)d_in[iEOW], (const float*)d_in[iEOB],
                                     (const float*)d_in[iATT], esrc);
    dst_kernel<<<N_DST/8, 256>>>((const float*)d_in[iNW], (const float*)d_in[iNB], out);
}